// round 6
// baseline (speedup 1.0000x reference)
#include <cuda_runtime.h>
#include <cuda_bf16.h>
#include <math.h>
#include <stdint.h>

typedef __nv_bfloat16 bf16;

// ---------------- fixed problem dims ----------------
#define BB   2
#define TT4  4
#define N4   4096
#define CC   256
#define NC   150
#define TNE  16384
#define HID  1024
#define NH   8
#define HD   32
#define HH   64
#define WW   64

#define OUT0_ELEMS 2097152
#define CXZ_ELEMS  4915200

// ---------------- scratch ----------------
__device__ float g_cl[4915200];       // (B*T, nc, N) fp32 (needed by prompt cos)
__device__ float g_cen[307200];
__device__ float g_cinln[76800];
__device__ float g_kbuf[76800];
__device__ float g_vbuf[76800];
__device__ float g_q[2097152];
__device__ float g_o[2097152];
__device__ float g_oproj[2097152];
__device__ float g_out1[2097152];
__device__ float g_h1[8388608];
__device__ float g_h2[2097152];

// bf16 hi/lo split buffers
__device__ bf16 g_xh[2097152],   g_xl[2097152];      // x  (n,c)
__device__ bf16 g_memh[6291456], g_meml[6291456];    // mem (n,c)
__device__ bf16 g_xth[2097152],  g_xtl[2097152];     // x^T (c,n)
__device__ bf16 g_memth[6291456], g_memtl[6291456];  // mem^T (c,n)
__device__ bf16 g_cwh[38400],    g_cwl[38400];
__device__ bf16 g_t1h[25600], g_t1l[25600], g_t2h[25600], g_t2l[25600]; // tdt^T padded 160x160
__device__ bf16 g_azth[5242880], g_aztl[5242880];    // (B, 16384, 160)
__device__ bf16 g_acth[5242880], g_actl[5242880];
__device__ bf16 g_softh[4915200], g_softl[4915200];  // (B*T, nc, N)
__device__ bf16 g_obh[2097152], g_obl[2097152];
__device__ bf16 g_o1h[2097152], g_o1l[2097152];
__device__ bf16 g_gh[8388608],  g_gl[8388608];
__device__ bf16 g_qwh[65536],  g_qwl[65536];
__device__ bf16 g_pwh[65536],  g_pwl[65536];
__device__ bf16 g_f1h[262144], g_f1l[262144];
__device__ bf16 g_f2h[262144], g_f2l[262144];

// ---------------- warp-level bf16 MMA ----------
__device__ __forceinline__ void mma16816(float* d, const uint32_t* a, const uint32_t* b) {
    asm volatile(
        "mma.sync.aligned.m16n8k16.row.col.f32.bf16.bf16.f32 "
        "{%0,%1,%2,%3}, {%4,%5,%6,%7}, {%8,%9}, {%0,%1,%2,%3};\n"
        : "+f"(d[0]), "+f"(d[1]), "+f"(d[2]), "+f"(d[3])
        : "r"(a[0]), "r"(a[1]), "r"(a[2]), "r"(a[3]), "r"(b[0]), "r"(b[1]));
}

#define SAS 40   // smem row stride in bf16 elems

// shared inner compute: one 32-deep K chunk, 3-term bf16-split
__device__ __forceinline__ void hmma_compute_chunk(
    bf16 (*sAh)[SAS], bf16 (*sAl)[SAS], bf16 (*sBh)[SAS], bf16 (*sBl)[SAS],
    int wm, int wn, int g, int tg, float (*acc)[8][4])
{
    #pragma unroll
    for (int ks = 0; ks < 2; ks++) {
        int kc = ks * 16 + tg * 2;
        uint32_t ah[2][4], al[2][4], bh[8][2], bl[8][2];
        #pragma unroll
        for (int mt = 0; mt < 2; mt++) {
            int r = wm * 32 + mt * 16 + g;
            ah[mt][0] = *(const uint32_t*)&sAh[r][kc];
            ah[mt][1] = *(const uint32_t*)&sAh[r + 8][kc];
            ah[mt][2] = *(const uint32_t*)&sAh[r][kc + 8];
            ah[mt][3] = *(const uint32_t*)&sAh[r + 8][kc + 8];
            al[mt][0] = *(const uint32_t*)&sAl[r][kc];
            al[mt][1] = *(const uint32_t*)&sAl[r + 8][kc];
            al[mt][2] = *(const uint32_t*)&sAl[r][kc + 8];
            al[mt][3] = *(const uint32_t*)&sAl[r + 8][kc + 8];
        }
        #pragma unroll
        for (int nt = 0; nt < 8; nt++) {
            int nr = wn * 64 + nt * 8 + g;
            bh[nt][0] = *(const uint32_t*)&sBh[nr][kc];
            bh[nt][1] = *(const uint32_t*)&sBh[nr][kc + 8];
            bl[nt][0] = *(const uint32_t*)&sBl[nr][kc];
            bl[nt][1] = *(const uint32_t*)&sBl[nr][kc + 8];
        }
        #pragma unroll
        for (int mt = 0; mt < 2; mt++)
            #pragma unroll
            for (int nt = 0; nt < 8; nt++) {
                mma16816(acc[mt][nt], ah[mt], bh[nt]);
                mma16816(acc[mt][nt], ah[mt], bl[nt]);
                mma16816(acc[mt][nt], al[mt], bh[nt]);
            }
    }
}

// ================= HMMA GEMM (biased; q/proj/fc1/fc2) =================
// C[M,Ntot] = ((Ah+Al) @ (Bh+Bl)^T + bias)*scale, M%128==0, Ntot%128==0, K%32==0
__global__ void __launch_bounds__(256)
hmma_gemm_kernel(const bf16* __restrict__ Ah, const bf16* __restrict__ Al,
                 const bf16* __restrict__ Bh, const bf16* __restrict__ Bl,
                 const float* __restrict__ bias, float* __restrict__ C,
                 int Ntot, int K, float scale)
{
    __shared__ bf16 sAh[128][SAS], sAl[128][SAS], sBh[128][SAS], sBl[128][SAS];
    int tid = threadIdx.x, wid = tid >> 5, lane = tid & 31;
    int wm = wid & 3, wn = wid >> 2;
    int g = lane >> 2, tg = lane & 3;
    int m0 = blockIdx.y * 128, n0 = blockIdx.x * 128;
    int lrow = tid >> 1, lhalf = (tid & 1) * 16;

    float acc[2][8][4] = {};
    uint4 pah0, pah1, pal0, pal1, pbh0, pbh1, pbl0, pbl1;

    auto gload = [&](int k0) {
        const bf16* pa_h = Ah + (size_t)(m0 + lrow) * K + k0 + lhalf;
        const bf16* pa_l = Al + (size_t)(m0 + lrow) * K + k0 + lhalf;
        const bf16* pb_h = Bh + (size_t)(n0 + lrow) * K + k0 + lhalf;
        const bf16* pb_l = Bl + (size_t)(n0 + lrow) * K + k0 + lhalf;
        pah0 = *(const uint4*)pa_h; pah1 = *(const uint4*)(pa_h + 8);
        pal0 = *(const uint4*)pa_l; pal1 = *(const uint4*)(pa_l + 8);
        pbh0 = *(const uint4*)pb_h; pbh1 = *(const uint4*)(pb_h + 8);
        pbl0 = *(const uint4*)pb_l; pbl1 = *(const uint4*)(pb_l + 8);
    };
    auto sstore = [&]() {
        *(uint4*)&sAh[lrow][lhalf] = pah0; *(uint4*)&sAh[lrow][lhalf + 8] = pah1;
        *(uint4*)&sAl[lrow][lhalf] = pal0; *(uint4*)&sAl[lrow][lhalf + 8] = pal1;
        *(uint4*)&sBh[lrow][lhalf] = pbh0; *(uint4*)&sBh[lrow][lhalf + 8] = pbh1;
        *(uint4*)&sBl[lrow][lhalf] = pbl0; *(uint4*)&sBl[lrow][lhalf + 8] = pbl1;
    };

    int nk = K >> 5;
    gload(0);
    for (int c = 0; c < nk; c++) {
        __syncthreads();
        sstore();
        __syncthreads();
        if (c + 1 < nk) gload((c + 1) << 5);
        hmma_compute_chunk(sAh, sAl, sBh, sBl, wm, wn, g, tg, acc);
    }

    #pragma unroll
    for (int mt = 0; mt < 2; mt++) {
        int r0 = m0 + wm * 32 + mt * 16 + g;
        #pragma unroll
        for (int nt = 0; nt < 8; nt++) {
            int col = n0 + wn * 64 + nt * 8 + tg * 2;
            float b0 = bias[col], b1 = bias[col + 1];
            float2 v0, v1;
            v0.x = (acc[mt][nt][0] + b0) * scale;
            v0.y = (acc[mt][nt][1] + b1) * scale;
            v1.x = (acc[mt][nt][2] + b0) * scale;
            v1.y = (acc[mt][nt][3] + b1) * scale;
            *(float2*)&C[(size_t)r0 * Ntot + col] = v0;
            *(float2*)&C[(size_t)(r0 + 8) * Ntot + col] = v1;
        }
    }
}

// ================= cl HMMA: cl[bt,k,n] = w[k,:]·xf[bt,n,:] =================
// grid (32 n-tiles, 2 m-tiles, 8 bt)
__global__ void __launch_bounds__(256)
cl_hmma_kernel(const bf16* __restrict__ cwh, const bf16* __restrict__ cwl,
               const bf16* __restrict__ xh, const bf16* __restrict__ xl,
               const bf16* __restrict__ memh, const bf16* __restrict__ meml,
               float* __restrict__ cl)
{
    __shared__ bf16 sAh[128][SAS], sAl[128][SAS], sBh[128][SAS], sBl[128][SAS];
    int bt = blockIdx.z, b = bt >> 2, t = bt & 3;
    const bf16* Bh = (t < 3) ? memh + (size_t)(b * 3 + t) * 1048576 : xh + (size_t)b * 1048576;
    const bf16* Bl = (t < 3) ? meml + (size_t)(b * 3 + t) * 1048576 : xl + (size_t)b * 1048576;
    float* Cp = cl + (size_t)bt * 614400;

    int tid = threadIdx.x, wid = tid >> 5, lane = tid & 31;
    int wm = wid & 3, wn = wid >> 2;
    int g = lane >> 2, tg = lane & 3;
    int m0 = blockIdx.y * 128, n0 = blockIdx.x * 128;
    int lrow = tid >> 1, lhalf = (tid & 1) * 16;
    bool aval = (m0 + lrow) < NC;

    float acc[2][8][4] = {};
    uint4 z4 = make_uint4(0, 0, 0, 0);
    uint4 pah0, pah1, pal0, pal1, pbh0, pbh1, pbl0, pbl1;

    auto gload = [&](int k0) {
        if (aval) {
            const bf16* pa_h = cwh + (size_t)(m0 + lrow) * CC + k0 + lhalf;
            const bf16* pa_l = cwl + (size_t)(m0 + lrow) * CC + k0 + lhalf;
            pah0 = *(const uint4*)pa_h; pah1 = *(const uint4*)(pa_h + 8);
            pal0 = *(const uint4*)pa_l; pal1 = *(const uint4*)(pa_l + 8);
        } else { pah0 = pah1 = pal0 = pal1 = z4; }
        const bf16* pb_h = Bh + (size_t)(n0 + lrow) * CC + k0 + lhalf;
        const bf16* pb_l = Bl + (size_t)(n0 + lrow) * CC + k0 + lhalf;
        pbh0 = *(const uint4*)pb_h; pbh1 = *(const uint4*)(pb_h + 8);
        pbl0 = *(const uint4*)pb_l; pbl1 = *(const uint4*)(pb_l + 8);
    };
    auto sstore = [&]() {
        *(uint4*)&sAh[lrow][lhalf] = pah0; *(uint4*)&sAh[lrow][lhalf + 8] = pah1;
        *(uint4*)&sAl[lrow][lhalf] = pal0; *(uint4*)&sAl[lrow][lhalf + 8] = pal1;
        *(uint4*)&sBh[lrow][lhalf] = pbh0; *(uint4*)&sBh[lrow][lhalf + 8] = pbh1;
        *(uint4*)&sBl[lrow][lhalf] = pbl0; *(uint4*)&sBl[lrow][lhalf + 8] = pbl1;
    };

    gload(0);
    for (int c = 0; c < 8; c++) {
        __syncthreads();
        sstore();
        __syncthreads();
        if (c + 1 < 8) gload((c + 1) << 5);
        hmma_compute_chunk(sAh, sAl, sBh, sBl, wm, wn, g, tg, acc);
    }

    #pragma unroll
    for (int mt = 0; mt < 2; mt++) {
        int r0 = m0 + wm * 32 + mt * 16 + g;
        #pragma unroll
        for (int nt = 0; nt < 8; nt++) {
            int col = n0 + wn * 64 + nt * 8 + tg * 2;
            if (r0 < NC)
                *(float2*)&Cp[(size_t)r0 * N4 + col] = make_float2(acc[mt][nt][0], acc[mt][nt][1]);
            if (r0 + 8 < NC)
                *(float2*)&Cp[(size_t)(r0 + 8) * N4 + col] = make_float2(acc[mt][nt][2], acc[mt][nt][3]);
        }
    }
}

// ================= comb HMMA: cxz[b,j,m] = sum_k tdt1[k,j]az[k,m] + tdt2[k,j]ac[k,m]
// A = tdt^T padded (160x160); B = az/ac transposed (16384 x 160). grid (128, 2, 2)
__global__ void __launch_bounds__(256)
comb_hmma_kernel(const bf16* __restrict__ t1h, const bf16* __restrict__ t1l,
                 const bf16* __restrict__ t2h, const bf16* __restrict__ t2l,
                 const bf16* __restrict__ azth, const bf16* __restrict__ aztl,
                 const bf16* __restrict__ acth, const bf16* __restrict__ actl,
                 float* __restrict__ cxz, float* __restrict__ ctr)
{
    __shared__ bf16 sAh[128][SAS], sAl[128][SAS], sBh[128][SAS], sBl[128][SAS];
    int b = blockIdx.z;
    int j0 = blockIdx.y * 128, n0 = blockIdx.x * 128;
    int tid = threadIdx.x, wid = tid >> 5, lane = tid & 31;
    int wm = wid & 3, wn = wid >> 2;
    int g = lane >> 2, tg = lane & 3;
    int lrow = tid >> 1, lhalf = (tid & 1) * 16;
    bool aval = (j0 + lrow) < NC;   // rows 150..159 are zero in buffer; >=160 out of bounds

    float acc[2][8][4] = {};
    uint4 z4 = make_uint4(0, 0, 0, 0);
    uint4 pah0, pah1, pal0, pal1, pbh0, pbh1, pbl0, pbl1;

    auto gload = [&](int c) {
        int s = c / 5, k0 = (c % 5) * 32;
        const bf16* Ah = s ? t2h : t1h;
        const bf16* Al = s ? t2l : t1l;
        const bf16* Bh = (s ? acth : azth) + (size_t)b * 16384 * 160;
        const bf16* Bl = (s ? actl : aztl) + (size_t)b * 16384 * 160;
        if (aval) {
            const bf16* pa_h = Ah + (size_t)(j0 + lrow) * 160 + k0 + lhalf;
            const bf16* pa_l = Al + (size_t)(j0 + lrow) * 160 + k0 + lhalf;
            pah0 = *(const uint4*)pa_h; pah1 = *(const uint4*)(pa_h + 8);
            pal0 = *(const uint4*)pa_l; pal1 = *(const uint4*)(pa_l + 8);
        } else { pah0 = pah1 = pal0 = pal1 = z4; }
        const bf16* pb_h = Bh + (size_t)(n0 + lrow) * 160 + k0 + lhalf;
        const bf16* pb_l = Bl + (size_t)(n0 + lrow) * 160 + k0 + lhalf;
        pbh0 = *(const uint4*)pb_h; pbh1 = *(const uint4*)(pb_h + 8);
        pbl0 = *(const uint4*)pb_l; pbl1 = *(const uint4*)(pb_l + 8);
    };
    auto sstore = [&]() {
        *(uint4*)&sAh[lrow][lhalf] = pah0; *(uint4*)&sAh[lrow][lhalf + 8] = pah1;
        *(uint4*)&sAl[lrow][lhalf] = pal0; *(uint4*)&sAl[lrow][lhalf + 8] = pal1;
        *(uint4*)&sBh[lrow][lhalf] = pbh0; *(uint4*)&sBh[lrow][lhalf + 8] = pbh1;
        *(uint4*)&sBl[lrow][lhalf] = pbl0; *(uint4*)&sBl[lrow][lhalf + 8] = pbl1;
    };

    gload(0);
    for (int c = 0; c < 10; c++) {
        __syncthreads();
        sstore();
        __syncthreads();
        if (c + 1 < 10) gload(c + 1);
        hmma_compute_chunk(sAh, sAl, sBh, sBl, wm, wn, g, tg, acc);
    }

    int t = n0 >> 12;
    #pragma unroll
    for (int mt = 0; mt < 2; mt++) {
        int r0 = j0 + wm * 32 + mt * 16 + g;
        #pragma unroll
        for (int nt = 0; nt < 8; nt++) {
            int col = n0 + wn * 64 + nt * 8 + tg * 2;
            int n = col & 4095;
            if (r0 < NC) {
                float2 v = make_float2(acc[mt][nt][0], acc[mt][nt][1]);
                *(float2*)&cxz[((size_t)b * NC + r0) * TNE + col] = v;
                *(float2*)&ctr[((size_t)(b * TT4 + t) * NC + r0) * N4 + n] = v;
            }
            if (r0 + 8 < NC) {
                float2 v = make_float2(acc[mt][nt][2], acc[mt][nt][3]);
                *(float2*)&cxz[((size_t)b * NC + r0 + 8) * TNE + col] = v;
                *(float2*)&ctr[((size_t)(b * TT4 + t) * NC + r0 + 8) * N4 + n] = v;
            }
        }
    }
}

// ================= cen HMMA (split-K, atomic): cen[bt,k,c] = sum_n soft[k,n]·xf^T[c,n]
// grid (2 c-tiles, 2 m-tiles, 64 = 8bt * 8split)
__global__ void __launch_bounds__(256)
cen_hmma_kernel(const bf16* __restrict__ softh, const bf16* __restrict__ softl,
                const bf16* __restrict__ xth, const bf16* __restrict__ xtl,
                const bf16* __restrict__ memth, const bf16* __restrict__ memtl,
                float* __restrict__ cen)
{
    __shared__ bf16 sAh[128][SAS], sAl[128][SAS], sBh[128][SAS], sBl[128][SAS];
    int bt = blockIdx.z >> 3, sp = blockIdx.z & 7;
    int b = bt >> 2, t = bt & 3;
    const bf16* Ah = softh + (size_t)bt * 614400;
    const bf16* Al = softl + (size_t)bt * 614400;
    const bf16* Bh = (t < 3) ? memth + (size_t)(b * 3 + t) * 1048576 : xth + (size_t)b * 1048576;
    const bf16* Bl = (t < 3) ? memtl + (size_t)(b * 3 + t) * 1048576 : xtl + (size_t)b * 1048576;
    float* Cp = cen + (size_t)bt * 38400;
    int koff = sp * 512;

    int tid = threadIdx.x, wid = tid >> 5, lane = tid & 31;
    int wm = wid & 3, wn = wid >> 2;
    int g = lane >> 2, tg = lane & 3;
    int m0 = blockIdx.y * 128, n0 = blockIdx.x * 128;
    int lrow = tid >> 1, lhalf = (tid & 1) * 16;
    bool aval = (m0 + lrow) < NC;

    float acc[2][8][4] = {};
    uint4 z4 = make_uint4(0, 0, 0, 0);
    uint4 pah0, pah1, pal0, pal1, pbh0, pbh1, pbl0, pbl1;

    auto gload = [&](int k0) {
        if (aval) {
            const bf16* pa_h = Ah + (size_t)(m0 + lrow) * N4 + koff + k0 + lhalf;
            const bf16* pa_l = Al + (size_t)(m0 + lrow) * N4 + koff + k0 + lhalf;
            pah0 = *(const uint4*)pa_h; pah1 = *(const uint4*)(pa_h + 8);
            pal0 = *(const uint4*)pa_l; pal1 = *(const uint4*)(pa_l + 8);
        } else { pah0 = pah1 = pal0 = pal1 = z4; }
        const bf16* pb_h = Bh + (size_t)(n0 + lrow) * N4 + koff + k0 + lhalf;
        const bf16* pb_l = Bl + (size_t)(n0 + lrow) * N4 + koff + k0 + lhalf;
        pbh0 = *(const uint4*)pb_h; pbh1 = *(const uint4*)(pb_h + 8);
        pbl0 = *(const uint4*)pb_l; pbl1 = *(const uint4*)(pb_l + 8);
    };
    auto sstore = [&]() {
        *(uint4*)&sAh[lrow][lhalf] = pah0; *(uint4*)&sAh[lrow][lhalf + 8] = pah1;
        *(uint4*)&sAl[lrow][lhalf] = pal0; *(uint4*)&sAl[lrow][lhalf + 8] = pal1;
        *(uint4*)&sBh[lrow][lhalf] = pbh0; *(uint4*)&sBh[lrow][lhalf + 8] = pbh1;
        *(uint4*)&sBl[lrow][lhalf] = pbl0; *(uint4*)&sBl[lrow][lhalf + 8] = pbl1;
    };

    gload(0);
    for (int c = 0; c < 16; c++) {
        __syncthreads();
        sstore();
        __syncthreads();
        if (c + 1 < 16) gload((c + 1) << 5);
        hmma_compute_chunk(sAh, sAl, sBh, sBl, wm, wn, g, tg, acc);
    }

    #pragma unroll
    for (int mt = 0; mt < 2; mt++) {
        int r0 = m0 + wm * 32 + mt * 16 + g;
        #pragma unroll
        for (int nt = 0; nt < 8; nt++) {
            int col = n0 + wn * 64 + nt * 8 + tg * 2;
            if (r0 < NC) {
                atomicAdd(&Cp[(size_t)r0 * CC + col], acc[mt][nt][0]);
                atomicAdd(&Cp[(size_t)r0 * CC + col + 1], acc[mt][nt][1]);
            }
            if (r0 + 8 < NC) {
                atomicAdd(&Cp[(size_t)(r0 + 8) * CC + col], acc[mt][nt][2]);
                atomicAdd(&Cp[(size_t)(r0 + 8) * CC + col + 1], acc[mt][nt][3]);
            }
        }
    }
}

// ---------------- fp32 -> bf16 hi/lo split ----------------
__global__ void cvt_split_kernel(const float* __restrict__ in,
                                 bf16* __restrict__ hi, bf16* __restrict__ lo, int n)
{
    int i = (blockIdx.x * blockDim.x + threadIdx.x) * 4;
    if (i >= n) return;
    float4 v = *(const float4*)(in + i);
    bf16 h0 = __float2bfloat16(v.x), h1 = __float2bfloat16(v.y);
    bf16 h2 = __float2bfloat16(v.z), h3 = __float2bfloat16(v.w);
    bf16 l0 = __float2bfloat16(v.x - __bfloat162float(h0));
    bf16 l1 = __float2bfloat16(v.y - __bfloat162float(h1));
    bf16 l2 = __float2bfloat16(v.z - __bfloat162float(h2));
    bf16 l3 = __float2bfloat16(v.w - __bfloat162float(h3));
    *(__nv_bfloat162*)(hi + i)     = __nv_bfloat162(h0, h1);
    *(__nv_bfloat162*)(hi + i + 2) = __nv_bfloat162(h2, h3);
    *(__nv_bfloat162*)(lo + i)     = __nv_bfloat162(l0, l1);
    *(__nv_bfloat162*)(lo + i + 2) = __nv_bfloat162(l2, l3);
}

// ---------------- transpose + split: (4096,256) -> (256,4096) hi/lo -------
// grid (128, 8, batch), block (32,8)
__global__ void transpose_split_kernel(const float* __restrict__ in,
                                       bf16* __restrict__ oh, bf16* __restrict__ ol)
{
    __shared__ float tile[32][33];
    const float* src = in + (size_t)blockIdx.z * 1048576;
    bf16* doh = oh + (size_t)blockIdx.z * 1048576;
    bf16* dol = ol + (size_t)blockIdx.z * 1048576;
    int tx = threadIdx.x, ty = threadIdx.y;
    int r0 = blockIdx.x * 32, c0 = blockIdx.y * 32;
    #pragma unroll
    for (int i = 0; i < 4; i++)
        tile[ty + i * 8][tx] = src[(size_t)(r0 + ty + i * 8) * CC + c0 + tx];
    __syncthreads();
    #pragma unroll
    for (int i = 0; i < 4; i++) {
        int c = c0 + ty + i * 8;
        float v = tile[tx][ty + i * 8];
        bf16 h = __float2bfloat16(v);
        doh[(size_t)c * N4 + r0 + tx] = h;
        dol[(size_t)c * N4 + r0 + tx] = __float2bfloat16(v - __bfloat162float(h));
    }
}

// ---------------- tdt^T padded split ----------------
__global__ void tdt_prep_kernel(const float* __restrict__ tdt1, const float* __restrict__ tdt2,
                                bf16* __restrict__ t1h, bf16* __restrict__ t1l,
                                bf16* __restrict__ t2h, bf16* __restrict__ t2l)
{
    int i = blockIdx.x * 256 + threadIdx.x;
    if (i >= 25600) return;
    int j = i / 160, k = i % 160;
    float v1 = (j < NC && k < NC) ? tdt1[k * NC + j] : 0.f;
    float v2 = (j < NC && k < NC) ? tdt2[k * NC + j] : 0.f;
    bf16 h1 = __float2bfloat16(v1), h2 = __float2bfloat16(v2);
    t1h[i] = h1; t1l[i] = __float2bfloat16(v1 - __bfloat162float(h1));
    t2h[i] = h2; t2l[i] = __float2bfloat16(v2 - __bfloat162float(h2));
}

// ---------------- helpers ----------------
__device__ __forceinline__ float block_reduce_sum(float v, float* sbuf) {
    int tid = threadIdx.x;
    sbuf[tid] = v; __syncthreads();
    for (int s = blockDim.x >> 1; s > 0; s >>= 1) {
        if (tid < s) sbuf[tid] += sbuf[tid + s];
        __syncthreads();
    }
    float r = sbuf[0]; __syncthreads();
    return r;
}
__device__ __forceinline__ float block_reduce_max(float v, float* sbuf) {
    int tid = threadIdx.x;
    sbuf[tid] = v; __syncthreads();
    for (int s = blockDim.x >> 1; s > 0; s >>= 1) {
        if (tid < s) sbuf[tid] = fmaxf(sbuf[tid], sbuf[tid + s]);
        __syncthreads();
    }
    float r = sbuf[0]; __syncthreads();
    return r;
}

// ======== generic 64x64 GEMM (tiny k/v projections) ====
#define OBM 64
#define OBN 64
#define OBK 16
__global__ void gemm_tb_kernel(const float* __restrict__ A,
                               const float* __restrict__ B,
                               const float* __restrict__ bias,
                               float* __restrict__ C,
                               int M, int N, int K, float scale)
{
    __shared__ float As[OBK][OBM];
    __shared__ float Bs[OBK][OBN];
    int tid = threadIdx.x;
    int tx = tid & 15, ty = tid >> 4;
    int m0 = blockIdx.y * OBM, n0 = blockIdx.x * OBN;
    float acc[4][4] = {};
    for (int k0 = 0; k0 < K; k0 += OBK) {
        #pragma unroll
        for (int j = 0; j < 4; j++) {
            int idx = tid + j * 256;
            int ml = idx / OBK, kl = idx % OBK;
            int m = m0 + ml, k = k0 + kl;
            As[kl][ml] = (m < M) ? A[(size_t)m * K + k] : 0.f;
        }
        #pragma unroll
        for (int j = 0; j < 4; j++) {
            int idx = tid + j * 256;
            int nl = idx / OBK, kl = idx % OBK;
            int n = n0 + nl, k = k0 + kl;
            Bs[kl][nl] = (n < N) ? B[(size_t)n * K + k] : 0.f;
        }
        __syncthreads();
        #pragma unroll
        for (int kk = 0; kk < OBK; kk++) {
            float a[4], b[4];
            *(float4*)a = *(const float4*)&As[kk][ty * 4];
            *(float4*)b = *(const float4*)&Bs[kk][tx * 4];
            #pragma unroll
            for (int i = 0; i < 4; i++)
                #pragma unroll
                for (int j = 0; j < 4; j++)
                    acc[i][j] += a[i] * b[j];
        }
        __syncthreads();
    }
    #pragma unroll
    for (int i = 0; i < 4; i++) {
        int m = m0 + ty * 4 + i;
        if (m >= M) continue;
        #pragma unroll
        for (int j = 0; j < 4; j++) {
            int n = n0 + tx * 4 + j;
            if (n >= N) continue;
            C[(size_t)m * N + n] = (acc[i][j] + bias[n]) * scale;
        }
    }
}

// ---- prompt scaling -> transposed bf16 hi/lo (row stride 160, zero-padded) ----
__global__ void prompt_scale_kernel(const float* __restrict__ z,
                                    const float* __restrict__ cl,
                                    const float* __restrict__ p1,
                                    const float* __restrict__ p2,
                                    bf16* __restrict__ azth, bf16* __restrict__ aztl,
                                    bf16* __restrict__ acth, bf16* __restrict__ actl)
{
    int m = blockIdx.x * blockDim.x + threadIdx.x;
    int b = blockIdx.z;
    if (m >= TNE) return;
    int t = m >> 12, n = m & 4095;
    const float* zrow = z + (size_t)b * NC * TNE + m;
    const float* crow = cl + ((size_t)(b * TT4 + t) * NC) * N4 + n;
    float dz = 0, nz = 0, dc = 0, ncs = 0, p1n = 0, p2n = 0;
    for (int k = 0; k < NC; k++) {
        float zv = zrow[(size_t)k * TNE];
        float cv = crow[(size_t)k * N4];
        float a = p1[k], bb = p2[k];
        dz += zv * a; nz += zv * zv; p1n += a * a;
        dc += cv * bb; ncs += cv * cv; p2n += bb * bb;
    }
    float cz = dz / (fmaxf(sqrtf(nz), 1e-12f) * fmaxf(sqrtf(p1n), 1e-12f));
    cz = fminf(fmaxf(cz, 0.f), 1.f) * 0.5f;
    float cc = dc / (fmaxf(sqrtf(ncs), 1e-12f) * fmaxf(sqrtf(p2n), 1e-12f));
    cc = fminf(fmaxf(cc, 0.f), 1.f) * 0.5f;

    size_t base = ((size_t)b * TNE + m) * 160;
    for (int k = 0; k < NC; k += 2) {
        float v0 = cz * zrow[(size_t)k * TNE];
        float v1 = cz * zrow[(size_t)(k + 1) * TNE];
        bf16 h0 = __float2bfloat16(v0), h1 = __float2bfloat16(v1);
        *(__nv_bfloat162*)(azth + base + k) = __nv_bfloat162(h0, h1);
        *(__nv_bfloat162*)(aztl + base + k) = __nv_bfloat162(
            __float2bfloat16(v0 - __bfloat162float(h0)),
            __float2bfloat16(v1 - __bfloat162float(h1)));
        float w0 = cc * crow[(size_t)k * N4];
        float w1 = cc * crow[(size_t)(k + 1) * N4];
        bf16 g0 = __float2bfloat16(w0), g1 = __float2bfloat16(w1);
        *(__nv_bfloat162*)(acth + base + k) = __nv_bfloat162(g0, g1);
        *(__nv_bfloat162*)(actl + base + k) = __nv_bfloat162(
            __float2bfloat16(w0 - __bfloat162float(g0)),
            __float2bfloat16(w1 - __bfloat162float(g1)));
    }
    __nv_bfloat162 zz = __nv_bfloat162(__float2bfloat16(0.f), __float2bfloat16(0.f));
    for (int k = NC; k < 160; k += 2) {
        *(__nv_bfloat162*)(azth + base + k) = zz;
        *(__nv_bfloat162*)(aztl + base + k) = zz;
        *(__nv_bfloat162*)(acth + base + k) = zz;
        *(__nv_bfloat162*)(actl + base + k) = zz;
    }
}

// ---- softmax -> bf16 hi/lo ----
__global__ void softmax_kernel(const float* __restrict__ cxz,
                               bf16* __restrict__ softh, bf16* __restrict__ softl)
{
    __shared__ float sbuf[256];
    int r = blockIdx.x;
    int k = r % NC;
    int bt = r / NC;
    int b = bt / TT4, t = bt % TT4;
    const float* src = cxz + ((size_t)b * NC + k) * TNE + t * N4;
    bf16* dh = softh + (size_t)r * N4;
    bf16* dl = softl + (size_t)r * N4;
    int tid = threadIdx.x;
    float mx = -3.4e38f;
    for (int i = tid; i < N4; i += 256) mx = fmaxf(mx, src[i]);
    mx = block_reduce_max(mx, sbuf);
    float s = 0.f;
    for (int i = tid; i < N4; i += 256) s += expf(src[i] - mx);
    s = block_reduce_sum(s, sbuf);
    float inv = 1.f / s;
    for (int i = tid; i < N4; i += 256) {
        float v = expf(src[i] - mx) * inv;
        bf16 h = __float2bfloat16(v);
        dh[i] = h;
        dl[i] = __float2bfloat16(v - __bfloat162float(h));
    }
}

// ---- zero cen ----
__global__ void zero_cen_kernel(float* __restrict__ cen)
{
    int i = blockIdx.x * blockDim.x + threadIdx.x;
    if (i < 307200) cen[i] = 0.f;
}

// ---- C_in gating + LayerNorm ----
__global__ void cin_kernel(const float* __restrict__ cen,
                           const float* __restrict__ alpha,
                           const float* __restrict__ beta,
                           const float* __restrict__ nw,
                           const float* __restrict__ nb,
                           float* __restrict__ cinln)
{
    __shared__ float sbuf[256];
    int bk = blockIdx.x;
    int b = bk / NC, k = bk % NC;
    int c = threadIdx.x;
    float last = cen[((size_t)(b * TT4 + 3) * NC + k) * CC + c];
    float pv[3];
    #pragma unroll
    for (int t = 0; t < 3; t++)
        pv[t] = cen[((size_t)(b * TT4 + t) * NC + k) * CC + c];
    float nl = block_reduce_sum(last * last, sbuf);
    float al = alpha[0], be = beta[0];
    float g[3];
    #pragma unroll
    for (int t = 0; t < 3; t++) {
        float dt = block_reduce_sum(last * pv[t], sbuf);
        float np = block_reduce_sum(pv[t] * pv[t], sbuf);
        float denom = fmaxf(sqrtf(nl) * sqrtf(np), 1e-8f);
        g[t] = 1.f / (1.f + expf(-(be + al * dt / denom)));
    }
    float cin = last + g[0] * pv[0] + g[1] * pv[1] + g[2] * pv[2];
    float mean = block_reduce_sum(cin, sbuf) * (1.f / CC);
    float d = cin - mean;
    float var = block_reduce_sum(d * d, sbuf) * (1.f / CC);
    cinln[((size_t)b * NC + k) * CC + c] = d * rsqrtf(var + 1e-5f) * nw[c] + nb[c];
}

// ---- attention ----
__global__ void attn_kernel(const float* __restrict__ q,
                            const float* __restrict__ kbuf,
                            const float* __restrict__ vbuf,
                            float* __restrict__ o)
{
    __shared__ float kh[NC * 33];
    __shared__ float vh[NC * 33];
    int b = blockIdx.z, h = blockIdx.y;
    int tid = threadIdx.x;
    int warp = tid >> 5, lane = tid & 31;
    for (int idx = tid; idx < NC * HD; idx += blockDim.x) {
        int kk = idx / HD, d = idx % HD;
        kh[kk * 33 + d] = kbuf[((size_t)b * NC + kk) * CC + h * HD + d];
        vh[kk * 33 + d] = vbuf[((size_t)b * NC + kk) * CC + h * HD + d];
    }
    __syncthreads();
    const unsigned FULL = 0xffffffffu;
    for (int ni = warp; ni < 256; ni += 8) {
        int n = blockIdx.x * 256 + ni;
        float qv = q[((size_t)b * N4 + n) * CC + h * HD + lane];
        float lg[5];
        #pragma unroll
        for (int i = 0; i < 5; i++) {
            int kk = lane + 32 * i;
            int kks = (kk < NC) ? kk : (NC - 1);
            float acc = 0.f;
            #pragma unroll
            for (int d = 0; d < 32; d++) {
                float qd = __shfl_sync(FULL, qv, d);
                acc += qd * kh[kks * 33 + d];
            }
            lg[i] = (kk < NC) ? acc : -3.4e38f;
        }
        float mx = lg[0];
        #pragma unroll
        for (int i = 1; i < 5; i++) mx = fmaxf(mx, lg[i]);
        #pragma unroll
        for (int off = 16; off > 0; off >>= 1)
            mx = fmaxf(mx, __shfl_xor_sync(FULL, mx, off));
        float p[5], s = 0.f;
        #pragma unroll
        for (int i = 0; i < 5; i++) { p[i] = expf(lg[i] - mx); s += p[i]; }
        #pragma unroll
        for (int off = 16; off > 0; off >>= 1)
            s += __shfl_xor_sync(FULL, s, off);
        float inv = 1.f / s;
        float od = 0.f;
        #pragma unroll
        for (int i = 0; i < 5; i++) {
            float pi = p[i] * inv;
            #pragma unroll
            for (int l = 0; l < 32; l++) {
                float a = __shfl_sync(FULL, pi, l);
                int kk = l + 32 * i;
                if (kk < NC) od += a * vh[kk * 33 + lane];
            }
        }
        o[((size_t)b * N4 + n) * CC + h * HD + lane] = od;
    }
}

// ---- out = base + LN(xin) ----
__global__ void ln_add_kernel(const float* __restrict__ base,
                              const float* __restrict__ xin,
                              const float* __restrict__ nw,
                              const float* __restrict__ nb,
                              float* __restrict__ out)
{
    __shared__ float sbuf[256];
    size_t row = blockIdx.x;
    int c = threadIdx.x;
    float v = xin[row * CC + c];
    float mean = block_reduce_sum(v, sbuf) * (1.f / CC);
    float d = v - mean;
    float var = block_reduce_sum(d * d, sbuf) * (1.f / CC);
    out[row * CC + c] = base[row * CC + c] + d * rsqrtf(var + 1e-5f) * nw[c] + nb[c];
}

// ---- out = base + LN(xin), + bf16 split ----
__global__ void ln_add_split_kernel(const float* __restrict__ base,
                                    const float* __restrict__ xin,
                                    const float* __restrict__ nw,
                                    const float* __restrict__ nb,
                                    float* __restrict__ out,
                                    bf16* __restrict__ ohi, bf16* __restrict__ olo)
{
    __shared__ float sbuf[256];
    size_t row = blockIdx.x;
    int c = threadIdx.x;
    float v = xin[row * CC + c];
    float mean = block_reduce_sum(v, sbuf) * (1.f / CC);
    float d = v - mean;
    float var = block_reduce_sum(d * d, sbuf) * (1.f / CC);
    float r = base[row * CC + c] + d * rsqrtf(var + 1e-5f) * nw[c] + nb[c];
    size_t idx = row * CC + c;
    out[idx] = r;
    bf16 h = __float2bfloat16(r);
    ohi[idx] = h;
    olo[idx] = __float2bfloat16(r - __bfloat162float(h));
}

// ---- depthwise conv + GELU -> bf16 hi/lo ----
__global__ void dwconv_gelu_bf16_kernel(const float* __restrict__ h1,
                                        const float* __restrict__ dw_w,
                                        const float* __restrict__ dw_b,
                                        bf16* __restrict__ gh, bf16* __restrict__ gl)
{
    int idx = blockIdx.x * blockDim.x + threadIdx.x;
    if (idx >= BB * N4 * HID) return;
    int ch = idx & (HID - 1);
    int r = idx >> 10;
    int n = r & (N4 - 1);
    int b = r >> 12;
    int y = n >> 6, x = n & 63;
    float acc = dw_b[ch];
    #pragma unroll
    for (int dy = 0; dy < 3; dy++) {
        int yy = y + dy - 1;
        if (yy < 0 || yy >= HH) continue;
        #pragma unroll
        for (int dx = 0; dx < 3; dx++) {
            int xx = x + dx - 1;
            if (xx < 0 || xx >= WW) continue;
            acc += h1[((size_t)b * N4 + yy * WW + xx) * HID + ch] *
                   dw_w[ch * 9 + dy * 3 + dx];
        }
    }
    float v = 0.5f * acc * (1.0f + erff(acc * 0.70710678118654752f));
    bf16 h = __float2bfloat16(v);
    gh[idx] = h;
    gl[idx] = __float2bfloat16(v - __bfloat162float(h));
}

// ================= host launcher =================
extern "C" void kernel_launch(void* const* d_in, const int* in_sizes, int n_in,
                              void* d_out, int out_size)
{
    const float* x      = (const float*)d_in[0];
    const float* z      = (const float*)d_in[1];
    const float* mem    = (const float*)d_in[2];
    const float* cw     = (const float*)d_in[3];
    const float* p1     = (const float*)d_in[4];
    const float* tdt1   = (const float*)d_in[5];
    const float* p2     = (const float*)d_in[6];
    const float* tdt2   = (const float*)d_in[7];
    const float* alpha  = (const float*)d_in[8];
    const float* beta   = (const float*)d_in[9];
    const float* q_w    = (const float*)d_in[10];
    const float* q_b    = (const float*)d_in[11];
    const float* k_w    = (const float*)d_in[12];
    const float* k_b    = (const float*)d_in[13];
    const float* v_w    = (const float*)d_in[14];
    const float* v_b    = (const float*)d_in[15];
    const float* proj_w = (const float*)d_in[16];
    const float* proj_b = (const float*)d_in[17];
    const float* norm_w = (const float*)d_in[18];
    const float* norm_b = (const float*)d_in[19];
    const float* fc1_w  = (const float*)d_in[20];
    const float* fc1_b  = (const float*)d_in[21];
    const float* dw_w   = (const float*)d_in[22];
    const float* dw_b   = (const float*)d_in[23];
    const float* fc2_w  = (const float*)d_in[24];
    const float* fc2_b  = (const float*)d_in[25];

    float* out0 = (float*)d_out;
    float* cxz  = out0 + OUT0_ELEMS;
    float* ctr  = out0 + OUT0_ELEMS + CXZ_ELEMS;

    float *cl, *cen, *cinln, *kb, *vb, *qb, *ob, *oproj, *out1, *h1, *h2;
    bf16 *xh, *xl, *memh, *meml, *xth, *xtl, *memth, *memtl, *cwh, *cwl;
    bf16 *t1h, *t1l, *t2h, *t2l, *azth, *aztl, *acth, *actl, *softh, *softl;
    bf16 *obh, *obl, *o1h, *o1l, *gh, *gl;
    bf16 *qwh, *qwl, *pwh, *pwl, *f1h, *f1l, *f2h, *f2l;
    cudaGetSymbolAddress((void**)&cl,    g_cl);
    cudaGetSymbolAddress((void**)&cen,   g_cen);
    cudaGetSymbolAddress((void**)&cinln, g_cinln);
    cudaGetSymbolAddress((void**)&kb,    g_kbuf);
    cudaGetSymbolAddress((void**)&vb,    g_vbuf);
    cudaGetSymbolAddress((void**)&qb,    g_q);
    cudaGetSymbolAddress((void**)&ob,    g_o);
    cudaGetSymbolAddress((void**)&oproj, g_oproj);
    cudaGetSymbolAddress((void**)&out1,  g_out1);
    cudaGetSymbolAddress((void**)&h1,    g_h1);
    cudaGetSymbolAddress((void**)&h2,    g_h2);
    cudaGetSymbolAddress((void**)&xh,   g_xh);   cudaGetSymbolAddress((void**)&xl,   g_xl);
    cudaGetSymbolAddress((void**)&memh, g_memh); cudaGetSymbolAddress((void**)&meml, g_meml);
    cudaGetSymbolAddress((void**)&xth,  g_xth);  cudaGetSymbolAddress((void**)&xtl,  g_xtl);
    cudaGetSymbolAddress((void**)&memth, g_memth); cudaGetSymbolAddress((void**)&memtl, g_memtl);
    cudaGetSymbolAddress((void**)&cwh,  g_cwh);  cudaGetSymbolAddress((void**)&cwl,  g_cwl);
    cudaGetSymbolAddress((void**)&t1h,  g_t1h);  cudaGetSymbolAddress((void**)&t1l,  g_t1l);
    cudaGetSymbolAddress((void**)&t2h,  g_t2h);  cudaGetSymbolAddress((void**)&t2l,  g_t2l);
    cudaGetSymbolAddress((void**)&azth, g_azth); cudaGetSymbolAddress((void**)&aztl, g_aztl);
    cudaGetSymbolAddress((void**)&acth, g_acth); cudaGetSymbolAddress((void**)&actl, g_actl);
    cudaGetSymbolAddress((void**)&softh, g_softh); cudaGetSymbolAddress((void**)&softl, g_softl);
    cudaGetSymbolAddress((void**)&obh, g_obh); cudaGetSymbolAddress((void**)&obl, g_obl);
    cudaGetSymbolAddress((void**)&o1h, g_o1h); cudaGetSymbolAddress((void**)&o1l, g_o1l);
    cudaGetSymbolAddress((void**)&gh,  g_gh);  cudaGetSymbolAddress((void**)&gl,  g_gl);
    cudaGetSymbolAddress((void**)&qwh, g_qwh); cudaGetSymbolAddress((void**)&qwl, g_qwl);
    cudaGetSymbolAddress((void**)&pwh, g_pwh); cudaGetSymbolAddress((void**)&pwl, g_pwl);
    cudaGetSymbolAddress((void**)&f1h, g_f1h); cudaGetSymbolAddress((void**)&f1l, g_f1l);
    cudaGetSymbolAddress((void**)&f2h, g_f2h); cudaGetSymbolAddress((void**)&f2l, g_f2l);

    // 0) prep: splits + transposes
    cvt_split_kernel<<<2097152 / 1024, 256>>>(x, xh, xl, 2097152);
    cvt_split_kernel<<<6291456 / 1024, 256>>>(mem, memh, meml, 6291456);
    cvt_split_kernel<<<65536 / 1024, 256>>>(q_w, qwh, qwl, 65536);
    cvt_split_kernel<<<65536 / 1024, 256>>>(proj_w, pwh, pwl, 65536);
    cvt_split_kernel<<<262144 / 1024, 256>>>(fc1_w, f1h, f1l, 262144);
    cvt_split_kernel<<<262144 / 1024, 256>>>(fc2_w, f2h, f2l, 262144);
    cvt_split_kernel<<<38, 256>>>(cw, cwh, cwl, 38400);
    tdt_prep_kernel<<<100, 256>>>(tdt1, tdt2, t1h, t1l, t2h, t2l);
    transpose_split_kernel<<<dim3(128, 8, 2), dim3(32, 8)>>>(x, xth, xtl);
    transpose_split_kernel<<<dim3(128, 8, 6), dim3(32, 8)>>>(mem, memth, memtl);

    // 1) cl (HMMA)
    cl_hmma_kernel<<<dim3(32, 2, 8), 256>>>(cwh, cwl, xh, xl, memh, meml, cl);
    // 2) prompt cos + scaling -> transposed bf16 az/ac
    prompt_scale_kernel<<<dim3(TNE / 256, 1, BB), 256>>>(z, cl, p1, p2, azth, aztl, acth, actl);
    // 3) combine (HMMA) -> cluster_x_z + center
    comb_hmma_kernel<<<dim3(128, 2, 2), 256>>>(t1h, t1l, t2h, t2l,
                                               azth, aztl, acth, actl, cxz, ctr);
    // 4) softmax -> bf16 hi/lo
    softmax_kernel<<<BB * TT4 * NC, 256>>>(cxz, softh, softl);
    // 5) cen (HMMA, split-K atomic)
    zero_cen_kernel<<<(307200 + 255) / 256, 256>>>(cen);
    cen_hmma_kernel<<<dim3(2, 2, 64), 256>>>(softh, softl, xth, xtl, memth, memtl, cen);
    // 6) gating + LN
    cin_kernel<<<BB * NC, 256>>>(cen, alpha, beta, norm_w, norm_b, cinln);
    // 7) k/v projections
    gemm_tb_kernel<<<dim3(CC / OBN, (BB * NC + OBM - 1) / OBM), 256>>>(
        cinln, k_w, k_b, kb, BB * NC, CC, CC, 1.f);
    gemm_tb_kernel<<<dim3(CC / OBN, (BB * NC + OBM - 1) / OBM), 256>>>(
        cinln, v_w, v_b, vb, BB * NC, CC, CC, 1.f);
    // 8) q projection
    hmma_gemm_kernel<<<dim3(2, 64), 256>>>(
        xh, xl, qwh, qwl, q_b, qb, CC, CC, 0.17677669529663687f);
    // 9) attention
    attn_kernel<<<dim3(N4 / 256, NH, BB), 256>>>(qb, kb, vb, ob);
    cvt_split_kernel<<<2097152 / 1024, 256>>>(ob, obh, obl, 2097152);
    // 10) output projection
    hmma_gemm_kernel<<<dim3(2, 64), 256>>>(
        obh, obl, pwh, pwl, proj_b, oproj, CC, CC, 1.f);
    // 11) out1 = x + LN(oproj), + split
    ln_add_split_kernel<<<BB * N4, 256>>>(x, oproj, norm_w, norm_b, out1, o1h, o1l);
    // 12) fc1
    hmma_gemm_kernel<<<dim3(8, 64), 256>>>(
        o1h, o1l, f1h, f1l, fc1_b, h1, HID, CC, 1.f);
    // 13) depthwise conv + gelu -> split
    dwconv_gelu_bf16_kernel<<<(BB * N4 * HID + 255) / 256, 256>>>(h1, dw_w, dw_b, gh, gl);
    // 14) fc2
    hmma_gemm_kernel<<<dim3(2, 64), 256>>>(
        gh, gl, f2h, f2l, fc2_b, h2, CC, HID, 1.f);
    // 15) out = out1 + LN(h2)
    ln_add_kernel<<<BB * N4, 256>>>(out1, h2, norm_w, norm_b, out0);
}

// round 7
// speedup vs baseline: 1.4290x; 1.4290x over previous
#include <cuda_runtime.h>
#include <cuda_bf16.h>
#include <math.h>
#include <stdint.h>

typedef __nv_bfloat16 bf16;

// ---------------- fixed problem dims ----------------
#define BB   2
#define TT4  4
#define N4   4096
#define CC   256
#define NC   150
#define TNE  16384
#define HID  1024
#define NH   8
#define HD   32
#define HH   64
#define WW   64

#define OUT0_ELEMS 2097152
#define CXZ_ELEMS  4915200

// ---------------- scratch ----------------
__device__ float g_cl[4915200];
__device__ float g_az[4915200];
__device__ float g_ac[4915200];
__device__ float g_cen[307200];
__device__ float g_cinln[76800];
__device__ float g_kbuf[76800];
__device__ float g_vbuf[76800];
__device__ float g_q[2097152];
__device__ float g_o[2097152];
__device__ float g_oproj[2097152];
__device__ float g_out1[2097152];
__device__ float g_h1[8388608];
__device__ float g_h2[2097152];

// bf16 hi/lo split buffers
__device__ bf16 g_xh[2097152],   g_xl[2097152];
__device__ bf16 g_memh[6291456], g_meml[6291456];
__device__ bf16 g_xth[2097152],  g_xtl[2097152];
__device__ bf16 g_memth[6291456], g_memtl[6291456];
__device__ bf16 g_cwh[38400],    g_cwl[38400];
__device__ bf16 g_softh[4915200], g_softl[4915200];
__device__ bf16 g_obh[2097152], g_obl[2097152];
__device__ bf16 g_o1h[2097152], g_o1l[2097152];
__device__ bf16 g_gh[8388608],  g_gl[8388608];
__device__ bf16 g_qwh[65536],  g_qwl[65536];
__device__ bf16 g_pwh[65536],  g_pwl[65536];
__device__ bf16 g_f1h[262144], g_f1l[262144];
__device__ bf16 g_f2h[262144], g_f2l[262144];

// ---------------- warp-level bf16 MMA ----------
__device__ __forceinline__ void mma16816(float* d, const uint32_t* a, const uint32_t* b) {
    asm volatile(
        "mma.sync.aligned.m16n8k16.row.col.f32.bf16.bf16.f32 "
        "{%0,%1,%2,%3}, {%4,%5,%6,%7}, {%8,%9}, {%0,%1,%2,%3};\n"
        : "+f"(d[0]), "+f"(d[1]), "+f"(d[2]), "+f"(d[3])
        : "r"(a[0]), "r"(a[1]), "r"(a[2]), "r"(a[3]), "r"(b[0]), "r"(b[1]));
}

#define SAS 40   // smem row stride in bf16 elems

// generic inner compute: WNT n-subtiles per warp
template<int WNT>
__device__ __forceinline__ void hmma_chunk(
    bf16 (*sAh)[SAS], bf16 (*sAl)[SAS], bf16 (*sBh)[SAS], bf16 (*sBl)[SAS],
    int wm, int wn, int g, int tg, float (*acc)[WNT][4])
{
    #pragma unroll
    for (int ks = 0; ks < 2; ks++) {
        int kc = ks * 16 + tg * 2;
        uint32_t ah[2][4], al[2][4], bh[WNT][2], bl[WNT][2];
        #pragma unroll
        for (int mt = 0; mt < 2; mt++) {
            int r = wm * 32 + mt * 16 + g;
            ah[mt][0] = *(const uint32_t*)&sAh[r][kc];
            ah[mt][1] = *(const uint32_t*)&sAh[r + 8][kc];
            ah[mt][2] = *(const uint32_t*)&sAh[r][kc + 8];
            ah[mt][3] = *(const uint32_t*)&sAh[r + 8][kc + 8];
            al[mt][0] = *(const uint32_t*)&sAl[r][kc];
            al[mt][1] = *(const uint32_t*)&sAl[r + 8][kc];
            al[mt][2] = *(const uint32_t*)&sAl[r][kc + 8];
            al[mt][3] = *(const uint32_t*)&sAl[r + 8][kc + 8];
        }
        #pragma unroll
        for (int nt = 0; nt < WNT; nt++) {
            int nr = wn * (WNT * 8) + nt * 8 + g;
            bh[nt][0] = *(const uint32_t*)&sBh[nr][kc];
            bh[nt][1] = *(const uint32_t*)&sBh[nr][kc + 8];
            bl[nt][0] = *(const uint32_t*)&sBl[nr][kc];
            bl[nt][1] = *(const uint32_t*)&sBl[nr][kc + 8];
        }
        #pragma unroll
        for (int mt = 0; mt < 2; mt++)
            #pragma unroll
            for (int nt = 0; nt < WNT; nt++) {
                mma16816(acc[mt][nt], ah[mt], bh[nt]);
                mma16816(acc[mt][nt], ah[mt], bl[nt]);
                mma16816(acc[mt][nt], al[mt], bh[nt]);
            }
    }
}

// ================= HMMA GEMM templated on BN (q/proj/fc1/fc2) ============
// C[M,Ntot] = ((Ah+Al) @ (Bh+Bl)^T + bias)*scale
template<int WNT>   // BN = 16*WNT
__global__ void __launch_bounds__(256)
hmma_gemm_kernel(const bf16* __restrict__ Ah, const bf16* __restrict__ Al,
                 const bf16* __restrict__ Bh, const bf16* __restrict__ Bl,
                 const float* __restrict__ bias, float* __restrict__ C,
                 int Ntot, int K, float scale)
{
    constexpr int BN = 16 * WNT;
    __shared__ bf16 sAh[128][SAS], sAl[128][SAS], sBh[BN][SAS], sBl[BN][SAS];
    int tid = threadIdx.x, wid = tid >> 5, lane = tid & 31;
    int wm = wid & 3, wn = wid >> 2;
    int g = lane >> 2, tg = lane & 3;
    int m0 = blockIdx.y * 128, n0 = blockIdx.x * BN;
    int lrow = tid >> 1, lhalf = (tid & 1) * 16;
    bool bload = tid < BN * 2;

    float acc[2][WNT][4];
    #pragma unroll
    for (int i = 0; i < 2; i++)
        #pragma unroll
        for (int j = 0; j < WNT; j++)
            #pragma unroll
            for (int k = 0; k < 4; k++) acc[i][j][k] = 0.f;

    uint4 pah0, pah1, pal0, pal1, pbh0, pbh1, pbl0, pbl1;
    auto gload = [&](int k0) {
        const bf16* pa_h = Ah + (size_t)(m0 + lrow) * K + k0 + lhalf;
        const bf16* pa_l = Al + (size_t)(m0 + lrow) * K + k0 + lhalf;
        pah0 = *(const uint4*)pa_h; pah1 = *(const uint4*)(pa_h + 8);
        pal0 = *(const uint4*)pa_l; pal1 = *(const uint4*)(pa_l + 8);
        if (bload) {
            const bf16* pb_h = Bh + (size_t)(n0 + lrow) * K + k0 + lhalf;
            const bf16* pb_l = Bl + (size_t)(n0 + lrow) * K + k0 + lhalf;
            pbh0 = *(const uint4*)pb_h; pbh1 = *(const uint4*)(pb_h + 8);
            pbl0 = *(const uint4*)pb_l; pbl1 = *(const uint4*)(pb_l + 8);
        }
    };
    auto sstore = [&]() {
        *(uint4*)&sAh[lrow][lhalf] = pah0; *(uint4*)&sAh[lrow][lhalf + 8] = pah1;
        *(uint4*)&sAl[lrow][lhalf] = pal0; *(uint4*)&sAl[lrow][lhalf + 8] = pal1;
        if (bload) {
            *(uint4*)&sBh[lrow][lhalf] = pbh0; *(uint4*)&sBh[lrow][lhalf + 8] = pbh1;
            *(uint4*)&sBl[lrow][lhalf] = pbl0; *(uint4*)&sBl[lrow][lhalf + 8] = pbl1;
        }
    };

    int nk = K >> 5;
    gload(0);
    for (int c = 0; c < nk; c++) {
        __syncthreads();
        sstore();
        __syncthreads();
        if (c + 1 < nk) gload((c + 1) << 5);
        hmma_chunk<WNT>(sAh, sAl, sBh, sBl, wm, wn, g, tg, acc);
    }

    #pragma unroll
    for (int mt = 0; mt < 2; mt++) {
        int r0 = m0 + wm * 32 + mt * 16 + g;
        #pragma unroll
        for (int nt = 0; nt < WNT; nt++) {
            int col = n0 + wn * (WNT * 8) + nt * 8 + tg * 2;
            float b0 = bias[col], b1 = bias[col + 1];
            float2 v0, v1;
            v0.x = (acc[mt][nt][0] + b0) * scale;
            v0.y = (acc[mt][nt][1] + b1) * scale;
            v1.x = (acc[mt][nt][2] + b0) * scale;
            v1.y = (acc[mt][nt][3] + b1) * scale;
            *(float2*)&C[(size_t)r0 * Ntot + col] = v0;
            *(float2*)&C[(size_t)(r0 + 8) * Ntot + col] = v1;
        }
    }
}

// ================= cl HMMA: cl[bt,k,n] = w[k,:]·xf[bt,n,:] =================
__global__ void __launch_bounds__(256)
cl_hmma_kernel(const bf16* __restrict__ cwh, const bf16* __restrict__ cwl,
               const bf16* __restrict__ xh, const bf16* __restrict__ xl,
               const bf16* __restrict__ memh, const bf16* __restrict__ meml,
               float* __restrict__ cl)
{
    __shared__ bf16 sAh[128][SAS], sAl[128][SAS], sBh[128][SAS], sBl[128][SAS];
    int bt = blockIdx.z, b = bt >> 2, t = bt & 3;
    const bf16* Bh = (t < 3) ? memh + (size_t)(b * 3 + t) * 1048576 : xh + (size_t)b * 1048576;
    const bf16* Bl = (t < 3) ? meml + (size_t)(b * 3 + t) * 1048576 : xl + (size_t)b * 1048576;
    float* Cp = cl + (size_t)bt * 614400;

    int tid = threadIdx.x, wid = tid >> 5, lane = tid & 31;
    int wm = wid & 3, wn = wid >> 2;
    int g = lane >> 2, tg = lane & 3;
    int m0 = blockIdx.y * 128, n0 = blockIdx.x * 128;
    int lrow = tid >> 1, lhalf = (tid & 1) * 16;
    bool aval = (m0 + lrow) < NC;

    float acc[2][8][4] = {};
    uint4 z4 = make_uint4(0, 0, 0, 0);
    uint4 pah0, pah1, pal0, pal1, pbh0, pbh1, pbl0, pbl1;

    auto gload = [&](int k0) {
        if (aval) {
            const bf16* pa_h = cwh + (size_t)(m0 + lrow) * CC + k0 + lhalf;
            const bf16* pa_l = cwl + (size_t)(m0 + lrow) * CC + k0 + lhalf;
            pah0 = *(const uint4*)pa_h; pah1 = *(const uint4*)(pa_h + 8);
            pal0 = *(const uint4*)pa_l; pal1 = *(const uint4*)(pa_l + 8);
        } else { pah0 = pah1 = pal0 = pal1 = z4; }
        const bf16* pb_h = Bh + (size_t)(n0 + lrow) * CC + k0 + lhalf;
        const bf16* pb_l = Bl + (size_t)(n0 + lrow) * CC + k0 + lhalf;
        pbh0 = *(const uint4*)pb_h; pbh1 = *(const uint4*)(pb_h + 8);
        pbl0 = *(const uint4*)pb_l; pbl1 = *(const uint4*)(pb_l + 8);
    };
    auto sstore = [&]() {
        *(uint4*)&sAh[lrow][lhalf] = pah0; *(uint4*)&sAh[lrow][lhalf + 8] = pah1;
        *(uint4*)&sAl[lrow][lhalf] = pal0; *(uint4*)&sAl[lrow][lhalf + 8] = pal1;
        *(uint4*)&sBh[lrow][lhalf] = pbh0; *(uint4*)&sBh[lrow][lhalf + 8] = pbh1;
        *(uint4*)&sBl[lrow][lhalf] = pbl0; *(uint4*)&sBl[lrow][lhalf + 8] = pbl1;
    };

    gload(0);
    for (int c = 0; c < 8; c++) {
        __syncthreads();
        sstore();
        __syncthreads();
        if (c + 1 < 8) gload((c + 1) << 5);
        hmma_chunk<8>(sAh, sAl, sBh, sBl, wm, wn, g, tg, acc);
    }

    #pragma unroll
    for (int mt = 0; mt < 2; mt++) {
        int r0 = m0 + wm * 32 + mt * 16 + g;
        #pragma unroll
        for (int nt = 0; nt < 8; nt++) {
            int col = n0 + wn * 64 + nt * 8 + tg * 2;
            if (r0 < NC)
                *(float2*)&Cp[(size_t)r0 * N4 + col] = make_float2(acc[mt][nt][0], acc[mt][nt][1]);
            if (r0 + 8 < NC)
                *(float2*)&Cp[(size_t)(r0 + 8) * N4 + col] = make_float2(acc[mt][nt][2], acc[mt][nt][3]);
        }
    }
}

// ================= cen HMMA (split-K, atomic) =================
__global__ void __launch_bounds__(256)
cen_hmma_kernel(const bf16* __restrict__ softh, const bf16* __restrict__ softl,
                const bf16* __restrict__ xth, const bf16* __restrict__ xtl,
                const bf16* __restrict__ memth, const bf16* __restrict__ memtl,
                float* __restrict__ cen)
{
    __shared__ bf16 sAh[128][SAS], sAl[128][SAS], sBh[128][SAS], sBl[128][SAS];
    int bt = blockIdx.z >> 3, sp = blockIdx.z & 7;
    int b = bt >> 2, t = bt & 3;
    const bf16* Ah = softh + (size_t)bt * 614400;
    const bf16* Al = softl + (size_t)bt * 614400;
    const bf16* Bh = (t < 3) ? memth + (size_t)(b * 3 + t) * 1048576 : xth + (size_t)b * 1048576;
    const bf16* Bl = (t < 3) ? memtl + (size_t)(b * 3 + t) * 1048576 : xtl + (size_t)b * 1048576;
    float* Cp = cen + (size_t)bt * 38400;
    int koff = sp * 512;

    int tid = threadIdx.x, wid = tid >> 5, lane = tid & 31;
    int wm = wid & 3, wn = wid >> 2;
    int g = lane >> 2, tg = lane & 3;
    int m0 = blockIdx.y * 128, n0 = blockIdx.x * 128;
    int lrow = tid >> 1, lhalf = (tid & 1) * 16;
    bool aval = (m0 + lrow) < NC;

    float acc[2][8][4] = {};
    uint4 z4 = make_uint4(0, 0, 0, 0);
    uint4 pah0, pah1, pal0, pal1, pbh0, pbh1, pbl0, pbl1;

    auto gload = [&](int k0) {
        if (aval) {
            const bf16* pa_h = Ah + (size_t)(m0 + lrow) * N4 + koff + k0 + lhalf;
            const bf16* pa_l = Al + (size_t)(m0 + lrow) * N4 + koff + k0 + lhalf;
            pah0 = *(const uint4*)pa_h; pah1 = *(const uint4*)(pa_h + 8);
            pal0 = *(const uint4*)pa_l; pal1 = *(const uint4*)(pa_l + 8);
        } else { pah0 = pah1 = pal0 = pal1 = z4; }
        const bf16* pb_h = Bh + (size_t)(n0 + lrow) * N4 + koff + k0 + lhalf;
        const bf16* pb_l = Bl + (size_t)(n0 + lrow) * N4 + koff + k0 + lhalf;
        pbh0 = *(const uint4*)pb_h; pbh1 = *(const uint4*)(pb_h + 8);
        pbl0 = *(const uint4*)pb_l; pbl1 = *(const uint4*)(pb_l + 8);
    };
    auto sstore = [&]() {
        *(uint4*)&sAh[lrow][lhalf] = pah0; *(uint4*)&sAh[lrow][lhalf + 8] = pah1;
        *(uint4*)&sAl[lrow][lhalf] = pal0; *(uint4*)&sAl[lrow][lhalf + 8] = pal1;
        *(uint4*)&sBh[lrow][lhalf] = pbh0; *(uint4*)&sBh[lrow][lhalf + 8] = pbh1;
        *(uint4*)&sBl[lrow][lhalf] = pbl0; *(uint4*)&sBl[lrow][lhalf + 8] = pbl1;
    };

    gload(0);
    for (int c = 0; c < 16; c++) {
        __syncthreads();
        sstore();
        __syncthreads();
        if (c + 1 < 16) gload((c + 1) << 5);
        hmma_chunk<8>(sAh, sAl, sBh, sBl, wm, wn, g, tg, acc);
    }

    #pragma unroll
    for (int mt = 0; mt < 2; mt++) {
        int r0 = m0 + wm * 32 + mt * 16 + g;
        #pragma unroll
        for (int nt = 0; nt < 8; nt++) {
            int col = n0 + wn * 64 + nt * 8 + tg * 2;
            if (r0 < NC) {
                atomicAdd(&Cp[(size_t)r0 * CC + col], acc[mt][nt][0]);
                atomicAdd(&Cp[(size_t)r0 * CC + col + 1], acc[mt][nt][1]);
            }
            if (r0 + 8 < NC) {
                atomicAdd(&Cp[(size_t)(r0 + 8) * CC + col], acc[mt][nt][2]);
                atomicAdd(&Cp[(size_t)(r0 + 8) * CC + col + 1], acc[mt][nt][3]);
            }
        }
    }
}

// ---------------- fp32 -> bf16 hi/lo split ----------------
__global__ void cvt_split_kernel(const float* __restrict__ in,
                                 bf16* __restrict__ hi, bf16* __restrict__ lo, int n)
{
    int i = (blockIdx.x * blockDim.x + threadIdx.x) * 4;
    if (i >= n) return;
    float4 v = *(const float4*)(in + i);
    bf16 h0 = __float2bfloat16(v.x), h1 = __float2bfloat16(v.y);
    bf16 h2 = __float2bfloat16(v.z), h3 = __float2bfloat16(v.w);
    bf16 l0 = __float2bfloat16(v.x - __bfloat162float(h0));
    bf16 l1 = __float2bfloat16(v.y - __bfloat162float(h1));
    bf16 l2 = __float2bfloat16(v.z - __bfloat162float(h2));
    bf16 l3 = __float2bfloat16(v.w - __bfloat162float(h3));
    *(__nv_bfloat162*)(hi + i)     = __nv_bfloat162(h0, h1);
    *(__nv_bfloat162*)(hi + i + 2) = __nv_bfloat162(h2, h3);
    *(__nv_bfloat162*)(lo + i)     = __nv_bfloat162(l0, l1);
    *(__nv_bfloat162*)(lo + i + 2) = __nv_bfloat162(l2, l3);
}

// ---------------- transpose + split: (4096,256) -> (256,4096) hi/lo -------
__global__ void transpose_split_kernel(const float* __restrict__ in,
                                       bf16* __restrict__ oh, bf16* __restrict__ ol)
{
    __shared__ float tile[32][33];
    const float* src = in + (size_t)blockIdx.z * 1048576;
    bf16* doh = oh + (size_t)blockIdx.z * 1048576;
    bf16* dol = ol + (size_t)blockIdx.z * 1048576;
    int tx = threadIdx.x, ty = threadIdx.y;
    int r0 = blockIdx.x * 32, c0 = blockIdx.y * 32;
    #pragma unroll
    for (int i = 0; i < 4; i++)
        tile[ty + i * 8][tx] = src[(size_t)(r0 + ty + i * 8) * CC + c0 + tx];
    __syncthreads();
    #pragma unroll
    for (int i = 0; i < 4; i++) {
        int c = c0 + ty + i * 8;
        float v = tile[tx][ty + i * 8];
        bf16 h = __float2bfloat16(v);
        doh[(size_t)c * N4 + r0 + tx] = h;
        dol[(size_t)c * N4 + r0 + tx] = __float2bfloat16(v - __bfloat162float(h));
    }
}

// ---------------- helpers ----------------
__device__ __forceinline__ float block_reduce_sum(float v, float* sbuf) {
    int tid = threadIdx.x;
    sbuf[tid] = v; __syncthreads();
    for (int s = blockDim.x >> 1; s > 0; s >>= 1) {
        if (tid < s) sbuf[tid] += sbuf[tid + s];
        __syncthreads();
    }
    float r = sbuf[0]; __syncthreads();
    return r;
}
__device__ __forceinline__ float block_reduce_max(float v, float* sbuf) {
    int tid = threadIdx.x;
    sbuf[tid] = v; __syncthreads();
    for (int s = blockDim.x >> 1; s > 0; s >>= 1) {
        if (tid < s) sbuf[tid] = fmaxf(sbuf[tid], sbuf[tid + s]);
        __syncthreads();
    }
    float r = sbuf[0]; __syncthreads();
    return r;
}

// ======== generic 64x64 fp32 GEMM (tiny k/v projections) ====
#define OBM 64
#define OBN 64
#define OBK 16
__global__ void gemm_tb_kernel(const float* __restrict__ A,
                               const float* __restrict__ B,
                               const float* __restrict__ bias,
                               float* __restrict__ C,
                               int M, int N, int K, float scale)
{
    __shared__ float As[OBK][OBM];
    __shared__ float Bs[OBK][OBN];
    int tid = threadIdx.x;
    int tx = tid & 15, ty = tid >> 4;
    int m0 = blockIdx.y * OBM, n0 = blockIdx.x * OBN;
    float acc[4][4] = {};
    for (int k0 = 0; k0 < K; k0 += OBK) {
        #pragma unroll
        for (int j = 0; j < 4; j++) {
            int idx = tid + j * 256;
            int ml = idx / OBK, kl = idx % OBK;
            int m = m0 + ml, k = k0 + kl;
            As[kl][ml] = (m < M) ? A[(size_t)m * K + k] : 0.f;
        }
        #pragma unroll
        for (int j = 0; j < 4; j++) {
            int idx = tid + j * 256;
            int nl = idx / OBK, kl = idx % OBK;
            int n = n0 + nl, k = k0 + kl;
            Bs[kl][nl] = (n < N) ? B[(size_t)n * K + k] : 0.f;
        }
        __syncthreads();
        #pragma unroll
        for (int kk = 0; kk < OBK; kk++) {
            float a[4], b[4];
            *(float4*)a = *(const float4*)&As[kk][ty * 4];
            *(float4*)b = *(const float4*)&Bs[kk][tx * 4];
            #pragma unroll
            for (int i = 0; i < 4; i++)
                #pragma unroll
                for (int j = 0; j < 4; j++)
                    acc[i][j] += a[i] * b[j];
        }
        __syncthreads();
    }
    #pragma unroll
    for (int i = 0; i < 4; i++) {
        int m = m0 + ty * 4 + i;
        if (m >= M) continue;
        #pragma unroll
        for (int j = 0; j < 4; j++) {
            int n = n0 + tx * 4 + j;
            if (n >= N) continue;
            C[(size_t)m * N + n] = (acc[i][j] + bias[n]) * scale;
        }
    }
}

// ---- prompt scaling (fp32 az/ac, coalesced along m) ----
__global__ void prompt_scale_kernel(const float* __restrict__ z,
                                    const float* __restrict__ cl,
                                    const float* __restrict__ p1,
                                    const float* __restrict__ p2,
                                    float* __restrict__ az,
                                    float* __restrict__ ac)
{
    int m = blockIdx.x * blockDim.x + threadIdx.x;
    int b = blockIdx.z;
    if (m >= TNE) return;
    int t = m >> 12, n = m & 4095;
    const float* zrow = z + (size_t)b * NC * TNE + m;
    const float* crow = cl + ((size_t)(b * TT4 + t) * NC) * N4 + n;
    float dz = 0, nz = 0, dc = 0, ncs = 0, p1n = 0, p2n = 0;
    for (int k = 0; k < NC; k++) {
        float zv = zrow[(size_t)k * TNE];
        float cv = crow[(size_t)k * N4];
        float a = p1[k], bb = p2[k];
        dz += zv * a; nz += zv * zv; p1n += a * a;
        dc += cv * bb; ncs += cv * cv; p2n += bb * bb;
    }
    float cz = dz / (fmaxf(sqrtf(nz), 1e-12f) * fmaxf(sqrtf(p1n), 1e-12f));
    cz = fminf(fmaxf(cz, 0.f), 1.f) * 0.5f;
    float cc = dc / (fmaxf(sqrtf(ncs), 1e-12f) * fmaxf(sqrtf(p2n), 1e-12f));
    cc = fminf(fmaxf(cc, 0.f), 1.f) * 0.5f;
    float* azp = az + (size_t)b * NC * TNE + m;
    float* acp = ac + (size_t)b * NC * TNE + m;
    for (int k = 0; k < NC; k++) {
        azp[(size_t)k * TNE] = cz * zrow[(size_t)k * TNE];
        acp[(size_t)k * TNE] = cc * crow[(size_t)k * N4];
    }
}

// ======== combine GEMM fp32 + fused center write ====
__global__ void __launch_bounds__(256)
comb_gemm2_kernel(const float* __restrict__ tdt1,
                  const float* __restrict__ tdt2,
                  const float* __restrict__ az,
                  const float* __restrict__ ac,
                  float* __restrict__ cxz,
                  float* __restrict__ ctr)
{
    constexpr int BK = 16;
    int b = blockIdx.z;
    int j0 = blockIdx.y * 64, m0 = blockIdx.x * 128;
    __shared__ float As[BK][68];
    __shared__ float Bs[BK][132];
    int tid = threadIdx.x;
    int tx = tid & 15, ty = tid >> 4;
    int kr = tid >> 4;
    int jc = (tid & 15) << 2;
    int kb = tid >> 5;
    int mc = (tid & 31) << 2;
    float acc[4][8] = {};
    for (int s = 0; s < 2; s++) {
        const float* tdt = s ? tdt2 : tdt1;
        const float* bz = (s ? ac : az) + (size_t)b * NC * TNE;
        for (int k0 = 0; k0 < NC; k0 += BK) {
            int kA = k0 + kr;
            float a0 = 0, a1 = 0, a2 = 0, a3 = 0;
            if (kA < NC) {
                int j = j0 + jc;
                a0 = (j + 0 < NC) ? tdt[(size_t)kA * NC + j + 0] : 0.f;
                a1 = (j + 1 < NC) ? tdt[(size_t)kA * NC + j + 1] : 0.f;
                a2 = (j + 2 < NC) ? tdt[(size_t)kA * NC + j + 2] : 0.f;
                a3 = (j + 3 < NC) ? tdt[(size_t)kA * NC + j + 3] : 0.f;
            }
            int kB0 = k0 + kb, kB1 = k0 + kb + 8;
            float4 bv0 = make_float4(0.f, 0.f, 0.f, 0.f);
            float4 bv1 = make_float4(0.f, 0.f, 0.f, 0.f);
            if (kB0 < NC) bv0 = *(const float4*)(bz + (size_t)kB0 * TNE + m0 + mc);
            if (kB1 < NC) bv1 = *(const float4*)(bz + (size_t)kB1 * TNE + m0 + mc);
            __syncthreads();
            As[kr][jc + 0] = a0; As[kr][jc + 1] = a1;
            As[kr][jc + 2] = a2; As[kr][jc + 3] = a3;
            Bs[kb][mc + 0] = bv0.x; Bs[kb][mc + 1] = bv0.y;
            Bs[kb][mc + 2] = bv0.z; Bs[kb][mc + 3] = bv0.w;
            Bs[kb + 8][mc + 0] = bv1.x; Bs[kb + 8][mc + 1] = bv1.y;
            Bs[kb + 8][mc + 2] = bv1.z; Bs[kb + 8][mc + 3] = bv1.w;
            __syncthreads();
            #pragma unroll
            for (int kk = 0; kk < BK; kk++) {
                float a[4], bb[8];
                *(float4*)&a[0]  = *(const float4*)&As[kk][ty * 4];
                *(float4*)&bb[0] = *(const float4*)&Bs[kk][tx * 8];
                *(float4*)&bb[4] = *(const float4*)&Bs[kk][tx * 8 + 4];
                #pragma unroll
                for (int i = 0; i < 4; i++)
                    #pragma unroll
                    for (int j = 0; j < 8; j++)
                        acc[i][j] += a[i] * bb[j];
            }
        }
    }
    int t = m0 / N4;
    int n = (m0 & (N4 - 1)) + tx * 8;
    #pragma unroll
    for (int i = 0; i < 4; i++) {
        int jj = j0 + ty * 4 + i;
        if (jj >= NC) continue;
        float* cp = cxz + ((size_t)b * NC + jj) * TNE + m0 + tx * 8;
        *(float4*)cp       = *(float4*)&acc[i][0];
        *(float4*)(cp + 4) = *(float4*)&acc[i][4];
        float* tp = ctr + ((size_t)(b * TT4 + t) * NC + jj) * N4 + n;
        *(float4*)tp       = *(float4*)&acc[i][0];
        *(float4*)(tp + 4) = *(float4*)&acc[i][4];
    }
}

// ---- softmax -> bf16 hi/lo ----
__global__ void softmax_kernel(const float* __restrict__ cxz,
                               bf16* __restrict__ softh, bf16* __restrict__ softl)
{
    __shared__ float sbuf[256];
    int r = blockIdx.x;
    int k = r % NC;
    int bt = r / NC;
    int b = bt / TT4, t = bt % TT4;
    const float* src = cxz + ((size_t)b * NC + k) * TNE + t * N4;
    bf16* dh = softh + (size_t)r * N4;
    bf16* dl = softl + (size_t)r * N4;
    int tid = threadIdx.x;
    float mx = -3.4e38f;
    for (int i = tid; i < N4; i += 256) mx = fmaxf(mx, src[i]);
    mx = block_reduce_max(mx, sbuf);
    float s = 0.f;
    float ev[16];
    #pragma unroll
    for (int j = 0; j < 16; j++) {
        int i = tid + j * 256;
        ev[j] = expf(src[i] - mx);
        s += ev[j];
    }
    s = block_reduce_sum(s, sbuf);
    float inv = 1.f / s;
    #pragma unroll
    for (int j = 0; j < 16; j++) {
        int i = tid + j * 256;
        float v = ev[j] * inv;
        bf16 h = __float2bfloat16(v);
        dh[i] = h;
        dl[i] = __float2bfloat16(v - __bfloat162float(h));
    }
}

// ---- zero cen ----
__global__ void zero_cen_kernel(float* __restrict__ cen)
{
    int i = blockIdx.x * blockDim.x + threadIdx.x;
    if (i < 307200) cen[i] = 0.f;
}

// ---- C_in gating + LayerNorm ----
__global__ void cin_kernel(const float* __restrict__ cen,
                           const float* __restrict__ alpha,
                           const float* __restrict__ beta,
                           const float* __restrict__ nw,
                           const float* __restrict__ nb,
                           float* __restrict__ cinln)
{
    __shared__ float sbuf[256];
    int bk = blockIdx.x;
    int b = bk / NC, k = bk % NC;
    int c = threadIdx.x;
    float last = cen[((size_t)(b * TT4 + 3) * NC + k) * CC + c];
    float pv[3];
    #pragma unroll
    for (int t = 0; t < 3; t++)
        pv[t] = cen[((size_t)(b * TT4 + t) * NC + k) * CC + c];
    float nl = block_reduce_sum(last * last, sbuf);
    float al = alpha[0], be = beta[0];
    float g[3];
    #pragma unroll
    for (int t = 0; t < 3; t++) {
        float dt = block_reduce_sum(last * pv[t], sbuf);
        float np = block_reduce_sum(pv[t] * pv[t], sbuf);
        float denom = fmaxf(sqrtf(nl) * sqrtf(np), 1e-8f);
        g[t] = 1.f / (1.f + expf(-(be + al * dt / denom)));
    }
    float cin = last + g[0] * pv[0] + g[1] * pv[1] + g[2] * pv[2];
    float mean = block_reduce_sum(cin, sbuf) * (1.f / CC);
    float d = cin - mean;
    float var = block_reduce_sum(d * d, sbuf) * (1.f / CC);
    cinln[((size_t)b * NC + k) * CC + c] = d * rsqrtf(var + 1e-5f) * nw[c] + nb[c];
}

// ---- attention ----
__global__ void attn_kernel(const float* __restrict__ q,
                            const float* __restrict__ kbuf,
                            const float* __restrict__ vbuf,
                            float* __restrict__ o)
{
    __shared__ float kh[NC * 33];
    __shared__ float vh[NC * 33];
    int b = blockIdx.z, h = blockIdx.y;
    int tid = threadIdx.x;
    int warp = tid >> 5, lane = tid & 31;
    for (int idx = tid; idx < NC * HD; idx += blockDim.x) {
        int kk = idx / HD, d = idx % HD;
        kh[kk * 33 + d] = kbuf[((size_t)b * NC + kk) * CC + h * HD + d];
        vh[kk * 33 + d] = vbuf[((size_t)b * NC + kk) * CC + h * HD + d];
    }
    __syncthreads();
    const unsigned FULL = 0xffffffffu;
    for (int ni = warp; ni < 256; ni += 8) {
        int n = blockIdx.x * 256 + ni;
        float qv = q[((size_t)b * N4 + n) * CC + h * HD + lane];
        float lg[5];
        #pragma unroll
        for (int i = 0; i < 5; i++) {
            int kk = lane + 32 * i;
            int kks = (kk < NC) ? kk : (NC - 1);
            float acc = 0.f;
            #pragma unroll
            for (int d = 0; d < 32; d++) {
                float qd = __shfl_sync(FULL, qv, d);
                acc += qd * kh[kks * 33 + d];
            }
            lg[i] = (kk < NC) ? acc : -3.4e38f;
        }
        float mx = lg[0];
        #pragma unroll
        for (int i = 1; i < 5; i++) mx = fmaxf(mx, lg[i]);
        #pragma unroll
        for (int off = 16; off > 0; off >>= 1)
            mx = fmaxf(mx, __shfl_xor_sync(FULL, mx, off));
        float p[5], s = 0.f;
        #pragma unroll
        for (int i = 0; i < 5; i++) { p[i] = expf(lg[i] - mx); s += p[i]; }
        #pragma unroll
        for (int off = 16; off > 0; off >>= 1)
            s += __shfl_xor_sync(FULL, s, off);
        float inv = 1.f / s;
        float od = 0.f;
        #pragma unroll
        for (int i = 0; i < 5; i++) {
            float pi = p[i] * inv;
            #pragma unroll
            for (int l = 0; l < 32; l++) {
                float a = __shfl_sync(FULL, pi, l);
                int kk = l + 32 * i;
                if (kk < NC) od += a * vh[kk * 33 + lane];
            }
        }
        o[((size_t)b * N4 + n) * CC + h * HD + lane] = od;
    }
}

// ---- out = base + LN(xin) ----
__global__ void ln_add_kernel(const float* __restrict__ base,
                              const float* __restrict__ xin,
                              const float* __restrict__ nw,
                              const float* __restrict__ nb,
                              float* __restrict__ out)
{
    __shared__ float sbuf[256];
    size_t row = blockIdx.x;
    int c = threadIdx.x;
    float v = xin[row * CC + c];
    float mean = block_reduce_sum(v, sbuf) * (1.f / CC);
    float d = v - mean;
    float var = block_reduce_sum(d * d, sbuf) * (1.f / CC);
    out[row * CC + c] = base[row * CC + c] + d * rsqrtf(var + 1e-5f) * nw[c] + nb[c];
}

// ---- out = base + LN(xin), + bf16 split ----
__global__ void ln_add_split_kernel(const float* __restrict__ base,
                                    const float* __restrict__ xin,
                                    const float* __restrict__ nw,
                                    const float* __restrict__ nb,
                                    float* __restrict__ out,
                                    bf16* __restrict__ ohi, bf16* __restrict__ olo)
{
    __shared__ float sbuf[256];
    size_t row = blockIdx.x;
    int c = threadIdx.x;
    float v = xin[row * CC + c];
    float mean = block_reduce_sum(v, sbuf) * (1.f / CC);
    float d = v - mean;
    float var = block_reduce_sum(d * d, sbuf) * (1.f / CC);
    float r = base[row * CC + c] + d * rsqrtf(var + 1e-5f) * nw[c] + nb[c];
    size_t idx = row * CC + c;
    out[idx] = r;
    bf16 h = __float2bfloat16(r);
    ohi[idx] = h;
    olo[idx] = __float2bfloat16(r - __bfloat162float(h));
}

// ---- depthwise conv + GELU -> bf16 hi/lo ----
__global__ void dwconv_gelu_bf16_kernel(const float* __restrict__ h1,
                                        const float* __restrict__ dw_w,
                                        const float* __restrict__ dw_b,
                                        bf16* __restrict__ gh, bf16* __restrict__ gl)
{
    int idx = blockIdx.x * blockDim.x + threadIdx.x;
    if (idx >= BB * N4 * HID) return;
    int ch = idx & (HID - 1);
    int r = idx >> 10;
    int n = r & (N4 - 1);
    int b = r >> 12;
    int y = n >> 6, x = n & 63;
    float acc = dw_b[ch];
    #pragma unroll
    for (int dy = 0; dy < 3; dy++) {
        int yy = y + dy - 1;
        if (yy < 0 || yy >= HH) continue;
        #pragma unroll
        for (int dx = 0; dx < 3; dx++) {
            int xx = x + dx - 1;
            if (xx < 0 || xx >= WW) continue;
            acc += h1[((size_t)b * N4 + yy * WW + xx) * HID + ch] *
                   dw_w[ch * 9 + dy * 3 + dx];
        }
    }
    float v = 0.5f * acc * (1.0f + erff(acc * 0.70710678118654752f));
    bf16 h = __float2bfloat16(v);
    gh[idx] = h;
    gl[idx] = __float2bfloat16(v - __bfloat162float(h));
}

// ================= host launcher =================
extern "C" void kernel_launch(void* const* d_in, const int* in_sizes, int n_in,
                              void* d_out, int out_size)
{
    const float* x      = (const float*)d_in[0];
    const float* z      = (const float*)d_in[1];
    const float* mem    = (const float*)d_in[2];
    const float* cw     = (const float*)d_in[3];
    const float* p1     = (const float*)d_in[4];
    const float* tdt1   = (const float*)d_in[5];
    const float* p2     = (const float*)d_in[6];
    const float* tdt2   = (const float*)d_in[7];
    const float* alpha  = (const float*)d_in[8];
    const float* beta   = (const float*)d_in[9];
    const float* q_w    = (const float*)d_in[10];
    const float* q_b    = (const float*)d_in[11];
    const float* k_w    = (const float*)d_in[12];
    const float* k_b    = (const float*)d_in[13];
    const float* v_w    = (const float*)d_in[14];
    const float* v_b    = (const float*)d_in[15];
    const float* proj_w = (const float*)d_in[16];
    const float* proj_b = (const float*)d_in[17];
    const float* norm_w = (const float*)d_in[18];
    const float* norm_b = (const float*)d_in[19];
    const float* fc1_w  = (const float*)d_in[20];
    const float* fc1_b  = (const float*)d_in[21];
    const float* dw_w   = (const float*)d_in[22];
    const float* dw_b   = (const float*)d_in[23];
    const float* fc2_w  = (const float*)d_in[24];
    const float* fc2_b  = (const float*)d_in[25];

    float* out0 = (float*)d_out;
    float* cxz  = out0 + OUT0_ELEMS;
    float* ctr  = out0 + OUT0_ELEMS + CXZ_ELEMS;

    float *cl, *az, *ac, *cen, *cinln, *kb, *vb, *qb, *ob, *oproj, *out1, *h1, *h2;
    bf16 *xh, *xl, *memh, *meml, *xth, *xtl, *memth, *memtl, *cwh, *cwl;
    bf16 *softh, *softl, *obh, *obl, *o1h, *o1l, *gh, *gl;
    bf16 *qwh, *qwl, *pwh, *pwl, *f1h, *f1l, *f2h, *f2l;
    cudaGetSymbolAddress((void**)&cl,    g_cl);
    cudaGetSymbolAddress((void**)&az,    g_az);
    cudaGetSymbolAddress((void**)&ac,    g_ac);
    cudaGetSymbolAddress((void**)&cen,   g_cen);
    cudaGetSymbolAddress((void**)&cinln, g_cinln);
    cudaGetSymbolAddress((void**)&kb,    g_kbuf);
    cudaGetSymbolAddress((void**)&vb,    g_vbuf);
    cudaGetSymbolAddress((void**)&qb,    g_q);
    cudaGetSymbolAddress((void**)&ob,    g_o);
    cudaGetSymbolAddress((void**)&oproj, g_oproj);
    cudaGetSymbolAddress((void**)&out1,  g_out1);
    cudaGetSymbolAddress((void**)&h1,    g_h1);
    cudaGetSymbolAddress((void**)&h2,    g_h2);
    cudaGetSymbolAddress((void**)&xh,   g_xh);   cudaGetSymbolAddress((void**)&xl,   g_xl);
    cudaGetSymbolAddress((void**)&memh, g_memh); cudaGetSymbolAddress((void**)&meml, g_meml);
    cudaGetSymbolAddress((void**)&xth,  g_xth);  cudaGetSymbolAddress((void**)&xtl,  g_xtl);
    cudaGetSymbolAddress((void**)&memth, g_memth); cudaGetSymbolAddress((void**)&memtl, g_memtl);
    cudaGetSymbolAddress((void**)&cwh,  g_cwh);  cudaGetSymbolAddress((void**)&cwl,  g_cwl);
    cudaGetSymbolAddress((void**)&softh, g_softh); cudaGetSymbolAddress((void**)&softl, g_softl);
    cudaGetSymbolAddress((void**)&obh, g_obh); cudaGetSymbolAddress((void**)&obl, g_obl);
    cudaGetSymbolAddress((void**)&o1h, g_o1h); cudaGetSymbolAddress((void**)&o1l, g_o1l);
    cudaGetSymbolAddress((void**)&gh,  g_gh);  cudaGetSymbolAddress((void**)&gl,  g_gl);
    cudaGetSymbolAddress((void**)&qwh, g_qwh); cudaGetSymbolAddress((void**)&qwl, g_qwl);
    cudaGetSymbolAddress((void**)&pwh, g_pwh); cudaGetSymbolAddress((void**)&pwl, g_pwl);
    cudaGetSymbolAddress((void**)&f1h, g_f1h); cudaGetSymbolAddress((void**)&f1l, g_f1l);
    cudaGetSymbolAddress((void**)&f2h, g_f2h); cudaGetSymbolAddress((void**)&f2l, g_f2l);

    // 0) prep: coalesced splits + tiled transposes
    cvt_split_kernel<<<2097152 / 1024, 256>>>(x, xh, xl, 2097152);
    cvt_split_kernel<<<6291456 / 1024, 256>>>(mem, memh, meml, 6291456);
    cvt_split_kernel<<<65536 / 1024, 256>>>(q_w, qwh, qwl, 65536);
    cvt_split_kernel<<<65536 / 1024, 256>>>(proj_w, pwh, pwl, 65536);
    cvt_split_kernel<<<262144 / 1024, 256>>>(fc1_w, f1h, f1l, 262144);
    cvt_split_kernel<<<262144 / 1024, 256>>>(fc2_w, f2h, f2l, 262144);
    cvt_split_kernel<<<38, 256>>>(cw, cwh, cwl, 38400);
    transpose_split_kernel<<<dim3(128, 8, 2), dim3(32, 8)>>>(x, xth, xtl);
    transpose_split_kernel<<<dim3(128, 8, 6), dim3(32, 8)>>>(mem, memth, memtl);

    // 1) cl (HMMA)
    cl_hmma_kernel<<<dim3(32, 2, 8), 256>>>(cwh, cwl, xh, xl, memh, meml, cl);
    // 2) prompt cos + scaling (fp32, coalesced)
    prompt_scale_kernel<<<dim3(TNE / 256, 1, BB), 256>>>(z, cl, p1, p2, az, ac);
    // 3) combine (fp32) -> cluster_x_z + center
    comb_gemm2_kernel<<<dim3(TNE / 128, 3, BB), 256>>>(tdt1, tdt2, az, ac, cxz, ctr);
    // 4) softmax -> bf16 hi/lo
    softmax_kernel<<<BB * TT4 * NC, 256>>>(cxz, softh, softl);
    // 5) cen (HMMA, split-K atomic)
    zero_cen_kernel<<<(307200 + 255) / 256, 256>>>(cen);
    cen_hmma_kernel<<<dim3(2, 2, 64), 256>>>(softh, softl, xth, xtl, memth, memtl, cen);
    // 6) gating + LN
    cin_kernel<<<BB * NC, 256>>>(cen, alpha, beta, norm_w, norm_b, cinln);
    // 7) k/v projections
    gemm_tb_kernel<<<dim3(CC / OBN, (BB * NC + OBM - 1) / OBM), 256>>>(
        cinln, k_w, k_b, kb, BB * NC, CC, CC, 1.f);
    gemm_tb_kernel<<<dim3(CC / OBN, (BB * NC + OBM - 1) / OBM), 256>>>(
        cinln, v_w, v_b, vb, BB * NC, CC, CC, 1.f);
    // 8) q projection (HMMA, BN=64)
    hmma_gemm_kernel<4><<<dim3(4, 64), 256>>>(
        xh, xl, qwh, qwl, q_b, qb, CC, CC, 0.17677669529663687f);
    // 9) attention
    attn_kernel<<<dim3(N4 / 256, NH, BB), 256>>>(qb, kb, vb, ob);
    cvt_split_kernel<<<2097152 / 1024, 256>>>(ob, obh, obl, 2097152);
    // 10) output projection (HMMA, BN=64)
    hmma_gemm_kernel<4><<<dim3(4, 64), 256>>>(
        obh, obl, pwh, pwl, proj_b, oproj, CC, CC, 1.f);
    // 11) out1 = x + LN(oproj), + split
    ln_add_split_kernel<<<BB * N4, 256>>>(x, oproj, norm_w, norm_b, out1, o1h, o1l);
    // 12) fc1 (HMMA, BN=128)
    hmma_gemm_kernel<8><<<dim3(8, 64), 256>>>(
        o1h, o1l, f1h, f1l, fc1_b, h1, HID, CC, 1.f);
    // 13) depthwise conv + gelu -> split
    dwconv_gelu_bf16_kernel<<<(BB * N4 * HID + 255) / 256, 256>>>(h1, dw_w, dw_b, gh, gl);
    // 14) fc2 (HMMA, BN=64)
    hmma_gemm_kernel<4><<<dim3(4, 64), 256>>>(
        gh, gl, f2h, f2l, fc2_b, h2, CC, HID, 1.f);
    // 15) out = out1 + LN(h2)
    ln_add_kernel<<<BB * N4, 256>>>(out1, h2, norm_w, norm_b, out0);
}

// round 8
// speedup vs baseline: 1.5777x; 1.1041x over previous
#include <cuda_runtime.h>
#include <cuda_bf16.h>
#include <math.h>
#include <stdint.h>

typedef __nv_bfloat16 bf16;

// ---------------- fixed problem dims ----------------
#define BB   2
#define TT4  4
#define N4   4096
#define CC   256
#define NC   150
#define TNE  16384
#define HID  1024
#define NH   8
#define HD   32
#define HH   64
#define WW   64

#define OUT0_ELEMS 2097152
#define CXZ_ELEMS  4915200

// ---------------- scratch ----------------
__device__ float g_cl[4915200];
__device__ float g_cz[32768], g_cc[32768];
__device__ float g_cen[307200];
__device__ float g_cinln[76800];
__device__ float g_kbuf[76800];
__device__ float g_vbuf[76800];
__device__ float g_q[2097152];
__device__ float g_oproj[2097152];
__device__ float g_out1[2097152];
__device__ float g_h1[8388608];
__device__ float g_h2[2097152];

// bf16 hi/lo split buffers
__device__ bf16 g_xh[2097152],   g_xl[2097152];
__device__ bf16 g_memh[6291456], g_meml[6291456];
__device__ bf16 g_xth[2097152],  g_xtl[2097152];
__device__ bf16 g_memth[6291456], g_memtl[6291456];
__device__ bf16 g_cwh[38400],    g_cwl[38400];
__device__ bf16 g_softh[4915200], g_softl[4915200];
__device__ bf16 g_obh[2097152], g_obl[2097152];
__device__ bf16 g_o1h[2097152], g_o1l[2097152];
__device__ bf16 g_gh[8388608],  g_gl[8388608];
__device__ bf16 g_qwh[65536],  g_qwl[65536];
__device__ bf16 g_pwh[65536],  g_pwl[65536];
__device__ bf16 g_f1h[262144], g_f1l[262144];
__device__ bf16 g_f2h[262144], g_f2l[262144];

// ---------------- warp-level bf16 MMA + cp.async ----------
__device__ __forceinline__ void mma16816(float* d, const uint32_t* a, const uint32_t* b) {
    asm volatile(
        "mma.sync.aligned.m16n8k16.row.col.f32.bf16.bf16.f32 "
        "{%0,%1,%2,%3}, {%4,%5,%6,%7}, {%8,%9}, {%0,%1,%2,%3};\n"
        : "+f"(d[0]), "+f"(d[1]), "+f"(d[2]), "+f"(d[3])
        : "r"(a[0]), "r"(a[1]), "r"(a[2]), "r"(a[3]), "r"(b[0]), "r"(b[1]));
}
__device__ __forceinline__ uint32_t smem_to_u32(const void* p) {
    uint32_t a;
    asm("{ .reg .u64 t; cvta.to.shared.u64 t, %1; cvt.u32.u64 %0, t; }"
        : "=r"(a) : "l"(p));
    return a;
}
__device__ __forceinline__ void cp_async16(uint32_t s, const void* g, bool v) {
    int sz = v ? 16 : 0;
    asm volatile("cp.async.cg.shared.global [%0], [%1], 16, %2;\n"
                 :: "r"(s), "l"(g), "r"(sz));
}
__device__ __forceinline__ void cp_commit() {
    asm volatile("cp.async.commit_group;\n" ::: "memory");
}
template<int N> __device__ __forceinline__ void cp_wait() {
    asm volatile("cp.async.wait_group %0;\n" :: "n"(N) : "memory");
}

#define SAS 40   // smem row stride in bf16 elems

// inner compute: WNT n-subtiles per warp, one 32-deep K chunk, 3-term split
template<int WNT>
__device__ __forceinline__ void hmma_chunk(
    bf16 (*sAh)[SAS], bf16 (*sAl)[SAS], bf16 (*sBh)[SAS], bf16 (*sBl)[SAS],
    int wm, int wn, int g, int tg, float (*acc)[WNT][4])
{
    #pragma unroll
    for (int ks = 0; ks < 2; ks++) {
        int kc = ks * 16 + tg * 2;
        uint32_t ah[2][4], al[2][4], bh[WNT][2], bl[WNT][2];
        #pragma unroll
        for (int mt = 0; mt < 2; mt++) {
            int r = wm * 32 + mt * 16 + g;
            ah[mt][0] = *(const uint32_t*)&sAh[r][kc];
            ah[mt][1] = *(const uint32_t*)&sAh[r + 8][kc];
            ah[mt][2] = *(const uint32_t*)&sAh[r][kc + 8];
            ah[mt][3] = *(const uint32_t*)&sAh[r + 8][kc + 8];
            al[mt][0] = *(const uint32_t*)&sAl[r][kc];
            al[mt][1] = *(const uint32_t*)&sAl[r + 8][kc];
            al[mt][2] = *(const uint32_t*)&sAl[r][kc + 8];
            al[mt][3] = *(const uint32_t*)&sAl[r + 8][kc + 8];
        }
        #pragma unroll
        for (int nt = 0; nt < WNT; nt++) {
            int nr = wn * (WNT * 8) + nt * 8 + g;
            bh[nt][0] = *(const uint32_t*)&sBh[nr][kc];
            bh[nt][1] = *(const uint32_t*)&sBh[nr][kc + 8];
            bl[nt][0] = *(const uint32_t*)&sBl[nr][kc];
            bl[nt][1] = *(const uint32_t*)&sBl[nr][kc + 8];
        }
        #pragma unroll
        for (int mt = 0; mt < 2; mt++)
            #pragma unroll
            for (int nt = 0; nt < WNT; nt++) {
                mma16816(acc[mt][nt], ah[mt], bh[nt]);
                mma16816(acc[mt][nt], ah[mt], bl[nt]);
                mma16816(acc[mt][nt], al[mt], bh[nt]);
            }
    }
}

// ---- 3-stage cp.async pipelined mainloop ----
template<int WNT, typename F>
__device__ __forceinline__ void hmma_pipe(char* sm, int nk, F getp, float (*acc)[WNT][4])
{
    constexpr int BN = 16 * WNT;
    constexpr int ASZ = 128 * SAS * 2;
    constexpr int BSZ = BN * SAS * 2;
    constexpr int STG = 2 * ASZ + 2 * BSZ;
    int tid = threadIdx.x;
    int wid = tid >> 5, lane = tid & 31;
    int wm = wid & 3, wn = wid >> 2, g = lane >> 2, tg = lane & 3;
    int lrow = tid >> 1, lhalf = (tid & 1) * 16;
    bool bload = (WNT == 8) || (tid < BN * 2);
    uint32_t sb = smem_to_u32(sm);
    uint32_t off = (uint32_t)(lrow * SAS + lhalf) * 2;

    auto issue = [&](int c) {
        uint32_t st = sb + (c % 3) * STG;
        const bf16 *ah, *al, *bh, *bl; bool av;
        getp(c, ah, al, bh, bl, av);
        cp_async16(st + off, ah, av);
        cp_async16(st + off + 16, ah + 8, av);
        cp_async16(st + ASZ + off, al, av);
        cp_async16(st + ASZ + off + 16, al + 8, av);
        if (bload) {
            cp_async16(st + 2 * ASZ + off, bh, true);
            cp_async16(st + 2 * ASZ + off + 16, bh + 8, true);
            cp_async16(st + 2 * ASZ + BSZ + off, bl, true);
            cp_async16(st + 2 * ASZ + BSZ + off + 16, bl + 8, true);
        }
        cp_commit();
    };

    issue(0); issue(1);
    for (int c = 0; c < nk; c++) {
        if (c + 2 <= nk) cp_wait<1>(); else cp_wait<0>();
        __syncthreads();
        {
            char* st = sm + (c % 3) * STG;
            bf16 (*sAh)[SAS] = (bf16(*)[SAS])st;
            bf16 (*sAl)[SAS] = (bf16(*)[SAS])(st + ASZ);
            bf16 (*sBh)[SAS] = (bf16(*)[SAS])(st + 2 * ASZ);
            bf16 (*sBl)[SAS] = (bf16(*)[SAS])(st + 2 * ASZ + BSZ);
            hmma_chunk<WNT>(sAh, sAl, sBh, sBl, wm, wn, g, tg, acc);
        }
        if (c + 2 < nk) issue(c + 2);
    }
}

// ================= HMMA GEMM (q/proj/fc1/fc2) ============
template<int WNT>
__global__ void __launch_bounds__(256)
hmma_gemm_kernel(const bf16* __restrict__ Ah, const bf16* __restrict__ Al,
                 const bf16* __restrict__ Bh, const bf16* __restrict__ Bl,
                 const float* __restrict__ bias, float* __restrict__ C,
                 int Ntot, int K, float scale)
{
    extern __shared__ char sm[];
    constexpr int BN = 16 * WNT;
    int tid = threadIdx.x, wid = tid >> 5, lane = tid & 31;
    int wm = wid & 3, wn = wid >> 2, g = lane >> 2, tg = lane & 3;
    int m0 = blockIdx.y * 128, n0 = blockIdx.x * BN;
    int lrow = tid >> 1, lhalf = (tid & 1) * 16;

    float acc[2][WNT][4] = {};
    auto getp = [&](int c, const bf16*& ah, const bf16*& al,
                    const bf16*& bh, const bf16*& bl, bool& av) {
        int k0 = (c << 5) + lhalf;
        ah = Ah + (size_t)(m0 + lrow) * K + k0;
        al = Al + (size_t)(m0 + lrow) * K + k0;
        bh = Bh + (size_t)(n0 + lrow) * K + k0;
        bl = Bl + (size_t)(n0 + lrow) * K + k0;
        av = true;
    };
    hmma_pipe<WNT>(sm, K >> 5, getp, acc);

    #pragma unroll
    for (int mt = 0; mt < 2; mt++) {
        int r0 = m0 + wm * 32 + mt * 16 + g;
        #pragma unroll
        for (int nt = 0; nt < WNT; nt++) {
            int col = n0 + wn * (WNT * 8) + nt * 8 + tg * 2;
            float b0 = bias[col], b1 = bias[col + 1];
            float2 v0, v1;
            v0.x = (acc[mt][nt][0] + b0) * scale;
            v0.y = (acc[mt][nt][1] + b1) * scale;
            v1.x = (acc[mt][nt][2] + b0) * scale;
            v1.y = (acc[mt][nt][3] + b1) * scale;
            *(float2*)&C[(size_t)r0 * Ntot + col] = v0;
            *(float2*)&C[(size_t)(r0 + 8) * Ntot + col] = v1;
        }
    }
}

// ================= cl HMMA =================
__global__ void __launch_bounds__(256)
cl_hmma_kernel(const bf16* __restrict__ cwh, const bf16* __restrict__ cwl,
               const bf16* __restrict__ xh, const bf16* __restrict__ xl,
               const bf16* __restrict__ memh, const bf16* __restrict__ meml,
               float* __restrict__ cl)
{
    extern __shared__ char sm[];
    int bt = blockIdx.z, b = bt >> 2, t = bt & 3;
    const bf16* Bh = (t < 3) ? memh + (size_t)(b * 3 + t) * 1048576 : xh + (size_t)b * 1048576;
    const bf16* Bl = (t < 3) ? meml + (size_t)(b * 3 + t) * 1048576 : xl + (size_t)b * 1048576;
    float* Cp = cl + (size_t)bt * 614400;

    int tid = threadIdx.x, wid = tid >> 5, lane = tid & 31;
    int wm = wid & 3, wn = wid >> 2, g = lane >> 2, tg = lane & 3;
    int m0 = blockIdx.y * 128, n0 = blockIdx.x * 128;
    int lrow = tid >> 1, lhalf = (tid & 1) * 16;
    bool aval = (m0 + lrow) < NC;

    float acc[2][8][4] = {};
    auto getp = [&](int c, const bf16*& ah, const bf16*& al,
                    const bf16*& bh, const bf16*& bl, bool& av) {
        int k0 = (c << 5) + lhalf;
        ah = cwh + (size_t)(m0 + lrow) * CC + k0;
        al = cwl + (size_t)(m0 + lrow) * CC + k0;
        bh = Bh + (size_t)(n0 + lrow) * CC + k0;
        bl = Bl + (size_t)(n0 + lrow) * CC + k0;
        av = aval;
    };
    hmma_pipe<8>(sm, 8, getp, acc);

    #pragma unroll
    for (int mt = 0; mt < 2; mt++) {
        int r0 = m0 + wm * 32 + mt * 16 + g;
        #pragma unroll
        for (int nt = 0; nt < 8; nt++) {
            int col = n0 + wn * 64 + nt * 8 + tg * 2;
            if (r0 < NC)
                *(float2*)&Cp[(size_t)r0 * N4 + col] = make_float2(acc[mt][nt][0], acc[mt][nt][1]);
            if (r0 + 8 < NC)
                *(float2*)&Cp[(size_t)(r0 + 8) * N4 + col] = make_float2(acc[mt][nt][2], acc[mt][nt][3]);
        }
    }
}

// ================= cen HMMA (split-K, atomic) =================
__global__ void __launch_bounds__(256)
cen_hmma_kernel(const bf16* __restrict__ softh, const bf16* __restrict__ softl,
                const bf16* __restrict__ xth, const bf16* __restrict__ xtl,
                const bf16* __restrict__ memth, const bf16* __restrict__ memtl,
                float* __restrict__ cen)
{
    extern __shared__ char sm[];
    int bt = blockIdx.z >> 3, sp = blockIdx.z & 7;
    int b = bt >> 2, t = bt & 3;
    const bf16* Ah = softh + (size_t)bt * 614400;
    const bf16* Al = softl + (size_t)bt * 614400;
    const bf16* Bh = (t < 3) ? memth + (size_t)(b * 3 + t) * 1048576 : xth + (size_t)b * 1048576;
    const bf16* Bl = (t < 3) ? memtl + (size_t)(b * 3 + t) * 1048576 : xtl + (size_t)b * 1048576;
    float* Cp = cen + (size_t)bt * 38400;
    int koff = sp * 512;

    int tid = threadIdx.x, wid = tid >> 5, lane = tid & 31;
    int wm = wid & 3, wn = wid >> 2, g = lane >> 2, tg = lane & 3;
    int m0 = blockIdx.y * 128, n0 = blockIdx.x * 128;
    int lrow = tid >> 1, lhalf = (tid & 1) * 16;
    bool aval = (m0 + lrow) < NC;

    float acc[2][8][4] = {};
    auto getp = [&](int c, const bf16*& ah, const bf16*& al,
                    const bf16*& bh, const bf16*& bl, bool& av) {
        int k0 = koff + (c << 5) + lhalf;
        ah = Ah + (size_t)(m0 + lrow) * N4 + k0;
        al = Al + (size_t)(m0 + lrow) * N4 + k0;
        bh = Bh + (size_t)(n0 + lrow) * N4 + k0;
        bl = Bl + (size_t)(n0 + lrow) * N4 + k0;
        av = aval;
    };
    hmma_pipe<8>(sm, 16, getp, acc);

    #pragma unroll
    for (int mt = 0; mt < 2; mt++) {
        int r0 = m0 + wm * 32 + mt * 16 + g;
        #pragma unroll
        for (int nt = 0; nt < 8; nt++) {
            int col = n0 + wn * 64 + nt * 8 + tg * 2;
            if (r0 < NC) {
                atomicAdd(&Cp[(size_t)r0 * CC + col], acc[mt][nt][0]);
                atomicAdd(&Cp[(size_t)r0 * CC + col + 1], acc[mt][nt][1]);
            }
            if (r0 + 8 < NC) {
                atomicAdd(&Cp[(size_t)(r0 + 8) * CC + col], acc[mt][nt][2]);
                atomicAdd(&Cp[(size_t)(r0 + 8) * CC + col + 1], acc[mt][nt][3]);
            }
        }
    }
}

// ---------------- fp32 -> bf16 hi/lo split ----------------
__device__ __forceinline__ void split_store4(const float4 v, bf16* hi, bf16* lo, int i) {
    bf16 h0 = __float2bfloat16(v.x), h1 = __float2bfloat16(v.y);
    bf16 h2 = __float2bfloat16(v.z), h3 = __float2bfloat16(v.w);
    *(__nv_bfloat162*)(hi + i)     = __nv_bfloat162(h0, h1);
    *(__nv_bfloat162*)(hi + i + 2) = __nv_bfloat162(h2, h3);
    *(__nv_bfloat162*)(lo + i) = __nv_bfloat162(
        __float2bfloat16(v.x - __bfloat162float(h0)),
        __float2bfloat16(v.y - __bfloat162float(h1)));
    *(__nv_bfloat162*)(lo + i + 2) = __nv_bfloat162(
        __float2bfloat16(v.z - __bfloat162float(h2)),
        __float2bfloat16(v.w - __bfloat162float(h3)));
}
__global__ void cvt_split_kernel(const float* __restrict__ in,
                                 bf16* __restrict__ hi, bf16* __restrict__ lo, int n)
{
    int i = (blockIdx.x * blockDim.x + threadIdx.x) * 4;
    if (i >= n) return;
    split_store4(*(const float4*)(in + i), hi, lo, i);
}
// merged weight splits
__global__ void cvt_split5_kernel(
    const float* a0, bf16* h0, bf16* l0, int s0,
    const float* a1, bf16* h1, bf16* l1, int s1,
    const float* a2, bf16* h2, bf16* l2, int s2,
    const float* a3, bf16* h3, bf16* l3, int s3,
    const float* a4, bf16* h4, bf16* l4, int s4)
{
    const float* in; bf16 *hi, *lo; int n;
    switch (blockIdx.y) {
        case 0: in = a0; hi = h0; lo = l0; n = s0; break;
        case 1: in = a1; hi = h1; lo = l1; n = s1; break;
        case 2: in = a2; hi = h2; lo = l2; n = s2; break;
        case 3: in = a3; hi = h3; lo = l3; n = s3; break;
        default: in = a4; hi = h4; lo = l4; n = s4; break;
    }
    int i = (blockIdx.x * 256 + threadIdx.x) * 4;
    if (i >= n) return;
    split_store4(*(const float4*)(in + i), hi, lo, i);
}

// ---------------- transpose + split ----------------
__global__ void transpose_split_kernel(const float* __restrict__ in,
                                       bf16* __restrict__ oh, bf16* __restrict__ ol)
{
    __shared__ float tile[32][33];
    const float* src = in + (size_t)blockIdx.z * 1048576;
    bf16* doh = oh + (size_t)blockIdx.z * 1048576;
    bf16* dol = ol + (size_t)blockIdx.z * 1048576;
    int tx = threadIdx.x, ty = threadIdx.y;
    int r0 = blockIdx.x * 32, c0 = blockIdx.y * 32;
    #pragma unroll
    for (int i = 0; i < 4; i++)
        tile[ty + i * 8][tx] = src[(size_t)(r0 + ty + i * 8) * CC + c0 + tx];
    __syncthreads();
    #pragma unroll
    for (int i = 0; i < 4; i++) {
        int c = c0 + ty + i * 8;
        float v = tile[tx][ty + i * 8];
        bf16 h = __float2bfloat16(v);
        doh[(size_t)c * N4 + r0 + tx] = h;
        dol[(size_t)c * N4 + r0 + tx] = __float2bfloat16(v - __bfloat162float(h));
    }
}

// ---------------- helpers ----------------
__device__ __forceinline__ float block_reduce_sum(float v, float* sbuf) {
    int tid = threadIdx.x;
    sbuf[tid] = v; __syncthreads();
    for (int s = blockDim.x >> 1; s > 0; s >>= 1) {
        if (tid < s) sbuf[tid] += sbuf[tid + s];
        __syncthreads();
    }
    float r = sbuf[0]; __syncthreads();
    return r;
}
__device__ __forceinline__ float block_reduce_max(float v, float* sbuf) {
    int tid = threadIdx.x;
    sbuf[tid] = v; __syncthreads();
    for (int s = blockDim.x >> 1; s > 0; s >>= 1) {
        if (tid < s) sbuf[tid] = fmaxf(sbuf[tid], sbuf[tid + s]);
        __syncthreads();
    }
    float r = sbuf[0]; __syncthreads();
    return r;
}

// ======== generic 64x64 fp32 GEMM (tiny k/v projections) ====
#define OBM 64
#define OBN 64
#define OBK 16
__global__ void gemm_tb_kernel(const float* __restrict__ A,
                               const float* __restrict__ B,
                               const float* __restrict__ bias,
                               float* __restrict__ C,
                               int M, int N, int K, float scale)
{
    __shared__ float As[OBK][OBM];
    __shared__ float Bs[OBK][OBN];
    int tid = threadIdx.x;
    int tx = tid & 15, ty = tid >> 4;
    int m0 = blockIdx.y * OBM, n0 = blockIdx.x * OBN;
    float acc[4][4] = {};
    for (int k0 = 0; k0 < K; k0 += OBK) {
        #pragma unroll
        for (int j = 0; j < 4; j++) {
            int idx = tid + j * 256;
            int ml = idx / OBK, kl = idx % OBK;
            int m = m0 + ml, k = k0 + kl;
            As[kl][ml] = (m < M) ? A[(size_t)m * K + k] : 0.f;
        }
        #pragma unroll
        for (int j = 0; j < 4; j++) {
            int idx = tid + j * 256;
            int nl = idx / OBK, kl = idx % OBK;
            int n = n0 + nl, k = k0 + kl;
            Bs[kl][nl] = (n < N) ? B[(size_t)n * K + k] : 0.f;
        }
        __syncthreads();
        #pragma unroll
        for (int kk = 0; kk < OBK; kk++) {
            float a[4], b[4];
            *(float4*)a = *(const float4*)&As[kk][ty * 4];
            *(float4*)b = *(const float4*)&Bs[kk][tx * 4];
            #pragma unroll
            for (int i = 0; i < 4; i++)
                #pragma unroll
                for (int j = 0; j < 4; j++)
                    acc[i][j] += a[i] * b[j];
        }
        __syncthreads();
    }
    #pragma unroll
    for (int i = 0; i < 4; i++) {
        int m = m0 + ty * 4 + i;
        if (m >= M) continue;
        #pragma unroll
        for (int j = 0; j < 4; j++) {
            int n = n0 + tx * 4 + j;
            if (n >= N) continue;
            C[(size_t)m * N + n] = (acc[i][j] + bias[n]) * scale;
        }
    }
}

// ---- prompt cos only -> cz/cc scale vectors ----
__global__ void prompt_scale_kernel(const float* __restrict__ z,
                                    const float* __restrict__ cl,
                                    const float* __restrict__ p1,
                                    const float* __restrict__ p2,
                                    float* __restrict__ cz,
                                    float* __restrict__ cc)
{
    int m = blockIdx.x * blockDim.x + threadIdx.x;
    int b = blockIdx.z;
    if (m >= TNE) return;
    int t = m >> 12, n = m & 4095;
    const float* zrow = z + (size_t)b * NC * TNE + m;
    const float* crow = cl + ((size_t)(b * TT4 + t) * NC) * N4 + n;
    float dz = 0, nz = 0, dc = 0, ncs = 0, p1n = 0, p2n = 0;
    for (int k = 0; k < NC; k++) {
        float zv = zrow[(size_t)k * TNE];
        float cv = crow[(size_t)k * N4];
        float a = p1[k], bb = p2[k];
        dz += zv * a; nz += zv * zv; p1n += a * a;
        dc += cv * bb; ncs += cv * cv; p2n += bb * bb;
    }
    float vz = dz / (fmaxf(sqrtf(nz), 1e-12f) * fmaxf(sqrtf(p1n), 1e-12f));
    float vc = dc / (fmaxf(sqrtf(ncs), 1e-12f) * fmaxf(sqrtf(p2n), 1e-12f));
    cz[(size_t)b * TNE + m] = fminf(fmaxf(vz, 0.f), 1.f) * 0.5f;
    cc[(size_t)b * TNE + m] = fminf(fmaxf(vc, 0.f), 1.f) * 0.5f;
}

// ======== combine GEMM fp32 (scale-on-load) + fused center write ====
__global__ void __launch_bounds__(256)
comb_gemm2_kernel(const float* __restrict__ tdt1,
                  const float* __restrict__ tdt2,
                  const float* __restrict__ z,
                  const float* __restrict__ cl,
                  const float* __restrict__ cz,
                  const float* __restrict__ cc,
                  float* __restrict__ cxz,
                  float* __restrict__ ctr)
{
    constexpr int BK = 16;
    int b = blockIdx.z;
    int j0 = blockIdx.y * 64, m0 = blockIdx.x * 128;
    __shared__ float As[BK][68];
    __shared__ float Bs[BK][132];
    int tid = threadIdx.x;
    int tx = tid & 15, ty = tid >> 4;
    int kr = tid >> 4;
    int jc = (tid & 15) << 2;
    int kb = tid >> 5;
    int mc = (tid & 31) << 2;
    int tt = m0 >> 12;
    int nbase = m0 & 4095;
    const float* zb = z + (size_t)b * NC * TNE + m0;
    const float* clb = cl + ((size_t)(b * TT4 + tt) * NC) * N4 + nbase;
    float4 czv = *(const float4*)(cz + (size_t)b * TNE + m0 + mc);
    float4 ccv = *(const float4*)(cc + (size_t)b * TNE + m0 + mc);
    float acc[4][8] = {};
    for (int s = 0; s < 2; s++) {
        const float* tdt = s ? tdt2 : tdt1;
        const float* bz = s ? clb : zb;
        size_t bstride = s ? (size_t)N4 : (size_t)TNE;
        float4 sc = s ? ccv : czv;
        for (int k0 = 0; k0 < NC; k0 += BK) {
            int kA = k0 + kr;
            float a0 = 0, a1 = 0, a2 = 0, a3 = 0;
            if (kA < NC) {
                int j = j0 + jc;
                a0 = (j + 0 < NC) ? tdt[(size_t)kA * NC + j + 0] : 0.f;
                a1 = (j + 1 < NC) ? tdt[(size_t)kA * NC + j + 1] : 0.f;
                a2 = (j + 2 < NC) ? tdt[(size_t)kA * NC + j + 2] : 0.f;
                a3 = (j + 3 < NC) ? tdt[(size_t)kA * NC + j + 3] : 0.f;
            }
            int kB0 = k0 + kb, kB1 = k0 + kb + 8;
            float4 bv0 = make_float4(0.f, 0.f, 0.f, 0.f);
            float4 bv1 = make_float4(0.f, 0.f, 0.f, 0.f);
            if (kB0 < NC) {
                bv0 = *(const float4*)(bz + (size_t)kB0 * bstride + mc);
                bv0.x *= sc.x; bv0.y *= sc.y; bv0.z *= sc.z; bv0.w *= sc.w;
            }
            if (kB1 < NC) {
                bv1 = *(const float4*)(bz + (size_t)kB1 * bstride + mc);
                bv1.x *= sc.x; bv1.y *= sc.y; bv1.z *= sc.z; bv1.w *= sc.w;
            }
            __syncthreads();
            As[kr][jc + 0] = a0; As[kr][jc + 1] = a1;
            As[kr][jc + 2] = a2; As[kr][jc + 3] = a3;
            Bs[kb][mc + 0] = bv0.x; Bs[kb][mc + 1] = bv0.y;
            Bs[kb][mc + 2] = bv0.z; Bs[kb][mc + 3] = bv0.w;
            Bs[kb + 8][mc + 0] = bv1.x; Bs[kb + 8][mc + 1] = bv1.y;
            Bs[kb + 8][mc + 2] = bv1.z; Bs[kb + 8][mc + 3] = bv1.w;
            __syncthreads();
            #pragma unroll
            for (int kk = 0; kk < BK; kk++) {
                float a[4], bb[8];
                *(float4*)&a[0]  = *(const float4*)&As[kk][ty * 4];
                *(float4*)&bb[0] = *(const float4*)&Bs[kk][tx * 8];
                *(float4*)&bb[4] = *(const float4*)&Bs[kk][tx * 8 + 4];
                #pragma unroll
                for (int i = 0; i < 4; i++)
                    #pragma unroll
                    for (int j = 0; j < 8; j++)
                        acc[i][j] += a[i] * bb[j];
            }
        }
    }
    int n = nbase + tx * 8;
    #pragma unroll
    for (int i = 0; i < 4; i++) {
        int jj = j0 + ty * 4 + i;
        if (jj >= NC) continue;
        float* cp = cxz + ((size_t)b * NC + jj) * TNE + m0 + tx * 8;
        *(float4*)cp       = *(float4*)&acc[i][0];
        *(float4*)(cp + 4) = *(float4*)&acc[i][4];
        float* tp = ctr + ((size_t)(b * TT4 + tt) * NC + jj) * N4 + n;
        *(float4*)tp       = *(float4*)&acc[i][0];
        *(float4*)(tp + 4) = *(float4*)&acc[i][4];
    }
}

// ---- softmax -> bf16 hi/lo ----
__global__ void softmax_kernel(const float* __restrict__ cxz,
                               bf16* __restrict__ softh, bf16* __restrict__ softl)
{
    __shared__ float sbuf[256];
    int r = blockIdx.x;
    int k = r % NC;
    int bt = r / NC;
    int b = bt / TT4, t = bt % TT4;
    const float* src = cxz + ((size_t)b * NC + k) * TNE + t * N4;
    bf16* dh = softh + (size_t)r * N4;
    bf16* dl = softl + (size_t)r * N4;
    int tid = threadIdx.x;
    float mx = -3.4e38f;
    for (int i = tid; i < N4; i += 256) mx = fmaxf(mx, src[i]);
    mx = block_reduce_max(mx, sbuf);
    float s = 0.f;
    float ev[16];
    #pragma unroll
    for (int j = 0; j < 16; j++) {
        int i = tid + j * 256;
        ev[j] = expf(src[i] - mx);
        s += ev[j];
    }
    s = block_reduce_sum(s, sbuf);
    float inv = 1.f / s;
    #pragma unroll
    for (int j = 0; j < 16; j++) {
        int i = tid + j * 256;
        float v = ev[j] * inv;
        bf16 h = __float2bfloat16(v);
        dh[i] = h;
        dl[i] = __float2bfloat16(v - __bfloat162float(h));
    }
}

// ---- zero cen ----
__global__ void zero_cen_kernel(float* __restrict__ cen)
{
    int i = blockIdx.x * blockDim.x + threadIdx.x;
    if (i < 307200) cen[i] = 0.f;
}

// ---- C_in gating + LayerNorm ----
__global__ void cin_kernel(const float* __restrict__ cen,
                           const float* __restrict__ alpha,
                           const float* __restrict__ beta,
                           const float* __restrict__ nw,
                           const float* __restrict__ nb,
                           float* __restrict__ cinln)
{
    __shared__ float sbuf[256];
    int bk = blockIdx.x;
    int b = bk / NC, k = bk % NC;
    int c = threadIdx.x;
    float last = cen[((size_t)(b * TT4 + 3) * NC + k) * CC + c];
    float pv[3];
    #pragma unroll
    for (int t = 0; t < 3; t++)
        pv[t] = cen[((size_t)(b * TT4 + t) * NC + k) * CC + c];
    float nl = block_reduce_sum(last * last, sbuf);
    float al = alpha[0], be = beta[0];
    float g[3];
    #pragma unroll
    for (int t = 0; t < 3; t++) {
        float dt = block_reduce_sum(last * pv[t], sbuf);
        float np = block_reduce_sum(pv[t] * pv[t], sbuf);
        float denom = fmaxf(sqrtf(nl) * sqrtf(np), 1e-8f);
        g[t] = 1.f / (1.f + expf(-(be + al * dt / denom)));
    }
    float cin = last + g[0] * pv[0] + g[1] * pv[1] + g[2] * pv[2];
    float mean = block_reduce_sum(cin, sbuf) * (1.f / CC);
    float d = cin - mean;
    float var = block_reduce_sum(d * d, sbuf) * (1.f / CC);
    cinln[((size_t)b * NC + k) * CC + c] = d * rsqrtf(var + 1e-5f) * nw[c] + nb[c];
}

// ---- attention -> bf16 hi/lo output ----
__global__ void attn_kernel(const float* __restrict__ q,
                            const float* __restrict__ kbuf,
                            const float* __restrict__ vbuf,
                            bf16* __restrict__ obh, bf16* __restrict__ obl)
{
    __shared__ float kh[NC * 33];
    __shared__ float vh[NC * 33];
    int b = blockIdx.z, h = blockIdx.y;
    int tid = threadIdx.x;
    int warp = tid >> 5, lane = tid & 31;
    for (int idx = tid; idx < NC * HD; idx += blockDim.x) {
        int kk = idx / HD, d = idx % HD;
        kh[kk * 33 + d] = kbuf[((size_t)b * NC + kk) * CC + h * HD + d];
        vh[kk * 33 + d] = vbuf[((size_t)b * NC + kk) * CC + h * HD + d];
    }
    __syncthreads();
    const unsigned FULL = 0xffffffffu;
    for (int ni = warp; ni < 256; ni += 8) {
        int n = blockIdx.x * 256 + ni;
        float qv = q[((size_t)b * N4 + n) * CC + h * HD + lane];
        float lg[5];
        #pragma unroll
        for (int i = 0; i < 5; i++) {
            int kk = lane + 32 * i;
            int kks = (kk < NC) ? kk : (NC - 1);
            float acc = 0.f;
            #pragma unroll
            for (int d = 0; d < 32; d++) {
                float qd = __shfl_sync(FULL, qv, d);
                acc += qd * kh[kks * 33 + d];
            }
            lg[i] = (kk < NC) ? acc : -3.4e38f;
        }
        float mx = lg[0];
        #pragma unroll
        for (int i = 1; i < 5; i++) mx = fmaxf(mx, lg[i]);
        #pragma unroll
        for (int off = 16; off > 0; off >>= 1)
            mx = fmaxf(mx, __shfl_xor_sync(FULL, mx, off));
        float p[5], s = 0.f;
        #pragma unroll
        for (int i = 0; i < 5; i++) { p[i] = expf(lg[i] - mx); s += p[i]; }
        #pragma unroll
        for (int off = 16; off > 0; off >>= 1)
            s += __shfl_xor_sync(FULL, s, off);
        float inv = 1.f / s;
        float od = 0.f;
        #pragma unroll
        for (int i = 0; i < 5; i++) {
            float pi = p[i] * inv;
            #pragma unroll
            for (int l = 0; l < 32; l++) {
                float a = __shfl_sync(FULL, pi, l);
                int kk = l + 32 * i;
                if (kk < NC) od += a * vh[kk * 33 + lane];
            }
        }
        size_t idx = ((size_t)b * N4 + n) * CC + h * HD + lane;
        bf16 hh = __float2bfloat16(od);
        obh[idx] = hh;
        obl[idx] = __float2bfloat16(od - __bfloat162float(hh));
    }
}

// ---- out = base + LN(xin) ----
__global__ void ln_add_kernel(const float* __restrict__ base,
                              const float* __restrict__ xin,
                              const float* __restrict__ nw,
                              const float* __restrict__ nb,
                              float* __restrict__ out)
{
    __shared__ float sbuf[256];
    size_t row = blockIdx.x;
    int c = threadIdx.x;
    float v = xin[row * CC + c];
    float mean = block_reduce_sum(v, sbuf) * (1.f / CC);
    float d = v - mean;
    float var = block_reduce_sum(d * d, sbuf) * (1.f / CC);
    out[row * CC + c] = base[row * CC + c] + d * rsqrtf(var + 1e-5f) * nw[c] + nb[c];
}

// ---- out = base + LN(xin), + bf16 split ----
__global__ void ln_add_split_kernel(const float* __restrict__ base,
                                    const float* __restrict__ xin,
                                    const float* __restrict__ nw,
                                    const float* __restrict__ nb,
                                    float* __restrict__ out,
                                    bf16* __restrict__ ohi, bf16* __restrict__ olo)
{
    __shared__ float sbuf[256];
    size_t row = blockIdx.x;
    int c = threadIdx.x;
    float v = xin[row * CC + c];
    float mean = block_reduce_sum(v, sbuf) * (1.f / CC);
    float d = v - mean;
    float var = block_reduce_sum(d * d, sbuf) * (1.f / CC);
    float r = base[row * CC + c] + d * rsqrtf(var + 1e-5f) * nw[c] + nb[c];
    size_t idx = row * CC + c;
    out[idx] = r;
    bf16 h = __float2bfloat16(r);
    ohi[idx] = h;
    olo[idx] = __float2bfloat16(r - __bfloat162float(h));
}

// ---- depthwise conv + GELU -> bf16 hi/lo ----
__global__ void dwconv_gelu_bf16_kernel(const float* __restrict__ h1,
                                        const float* __restrict__ dw_w,
                                        const float* __restrict__ dw_b,
                                        bf16* __restrict__ gh, bf16* __restrict__ gl)
{
    int idx = blockIdx.x * blockDim.x + threadIdx.x;
    if (idx >= BB * N4 * HID) return;
    int ch = idx & (HID - 1);
    int r = idx >> 10;
    int n = r & (N4 - 1);
    int b = r >> 12;
    int y = n >> 6, x = n & 63;
    float acc = dw_b[ch];
    #pragma unroll
    for (int dy = 0; dy < 3; dy++) {
        int yy = y + dy - 1;
        if (yy < 0 || yy >= HH) continue;
        #pragma unroll
        for (int dx = 0; dx < 3; dx++) {
            int xx = x + dx - 1;
            if (xx < 0 || xx >= WW) continue;
            acc += h1[((size_t)b * N4 + yy * WW + xx) * HID + ch] *
                   dw_w[ch * 9 + dy * 3 + dx];
        }
    }
    float v = 0.5f * acc * (1.0f + erff(acc * 0.70710678118654752f));
    bf16 h = __float2bfloat16(v);
    gh[idx] = h;
    gl[idx] = __float2bfloat16(v - __bfloat162float(h));
}

// ================= host launcher =================
#define SMEM_W4  92160    // 3 stages * (2*10240 + 2*5120)
#define SMEM_W8  122880   // 3 stages * (2*10240 + 2*10240)

extern "C" void kernel_launch(void* const* d_in, const int* in_sizes, int n_in,
                              void* d_out, int out_size)
{
    const float* x      = (const float*)d_in[0];
    const float* z      = (const float*)d_in[1];
    const float* mem    = (const float*)d_in[2];
    const float* cw     = (const float*)d_in[3];
    const float* p1     = (const float*)d_in[4];
    const float* tdt1   = (const float*)d_in[5];
    const float* p2     = (const float*)d_in[6];
    const float* tdt2   = (const float*)d_in[7];
    const float* alpha  = (const float*)d_in[8];
    const float* beta   = (const float*)d_in[9];
    const float* q_w    = (const float*)d_in[10];
    const float* q_b    = (const float*)d_in[11];
    const float* k_w    = (const float*)d_in[12];
    const float* k_b    = (const float*)d_in[13];
    const float* v_w    = (const float*)d_in[14];
    const float* v_b    = (const float*)d_in[15];
    const float* proj_w = (const float*)d_in[16];
    const float* proj_b = (const float*)d_in[17];
    const float* norm_w = (const float*)d_in[18];
    const float* norm_b = (const float*)d_in[19];
    const float* fc1_w  = (const float*)d_in[20];
    const float* fc1_b  = (const float*)d_in[21];
    const float* dw_w   = (const float*)d_in[22];
    const float* dw_b   = (const float*)d_in[23];
    const float* fc2_w  = (const float*)d_in[24];
    const float* fc2_b  = (const float*)d_in[25];

    float* out0 = (float*)d_out;
    float* cxz  = out0 + OUT0_ELEMS;
    float* ctr  = out0 + OUT0_ELEMS + CXZ_ELEMS;

    float *cl, *cz, *cc, *cen, *cinln, *kb, *vb, *qb, *oproj, *out1, *h1, *h2;
    bf16 *xh, *xl, *memh, *meml, *xth, *xtl, *memth, *memtl, *cwh, *cwl;
    bf16 *softh, *softl, *obh, *obl, *o1h, *o1l, *gh, *gl;
    bf16 *qwh, *qwl, *pwh, *pwl, *f1h, *f1l, *f2h, *f2l;
    cudaGetSymbolAddress((void**)&cl,    g_cl);
    cudaGetSymbolAddress((void**)&cz,    g_cz);
    cudaGetSymbolAddress((void**)&cc,    g_cc);
    cudaGetSymbolAddress((void**)&cen,   g_cen);
    cudaGetSymbolAddress((void**)&cinln, g_cinln);
    cudaGetSymbolAddress((void**)&kb,    g_kbuf);
    cudaGetSymbolAddress((void**)&vb,    g_vbuf);
    cudaGetSymbolAddress((void**)&qb,    g_q);
    cudaGetSymbolAddress((void**)&oproj, g_oproj);
    cudaGetSymbolAddress((void**)&out1,  g_out1);
    cudaGetSymbolAddress((void**)&h1,    g_h1);
    cudaGetSymbolAddress((void**)&h2,    g_h2);
    cudaGetSymbolAddress((void**)&xh,   g_xh);   cudaGetSymbolAddress((void**)&xl,   g_xl);
    cudaGetSymbolAddress((void**)&memh, g_memh); cudaGetSymbolAddress((void**)&meml, g_meml);
    cudaGetSymbolAddress((void**)&xth,  g_xth);  cudaGetSymbolAddress((void**)&xtl,  g_xtl);
    cudaGetSymbolAddress((void**)&memth, g_memth); cudaGetSymbolAddress((void**)&memtl, g_memtl);
    cudaGetSymbolAddress((void**)&cwh,  g_cwh);  cudaGetSymbolAddress((void**)&cwl,  g_cwl);
    cudaGetSymbolAddress((void**)&softh, g_softh); cudaGetSymbolAddress((void**)&softl, g_softl);
    cudaGetSymbolAddress((void**)&obh, g_obh); cudaGetSymbolAddress((void**)&obl, g_obl);
    cudaGetSymbolAddress((void**)&o1h, g_o1h); cudaGetSymbolAddress((void**)&o1l, g_o1l);
    cudaGetSymbolAddress((void**)&gh,  g_gh);  cudaGetSymbolAddress((void**)&gl,  g_gl);
    cudaGetSymbolAddress((void**)&qwh, g_qwh); cudaGetSymbolAddress((void**)&qwl, g_qwl);
    cudaGetSymbolAddress((void**)&pwh, g_pwh); cudaGetSymbolAddress((void**)&pwl, g_pwl);
    cudaGetSymbolAddress((void**)&f1h, g_f1h); cudaGetSymbolAddress((void**)&f1l, g_f1l);
    cudaGetSymbolAddress((void**)&f2h, g_f2h); cudaGetSymbolAddress((void**)&f2l, g_f2l);

    cudaFuncSetAttribute(hmma_gemm_kernel<4>,
                         cudaFuncAttributeMaxDynamicSharedMemorySize, SMEM_W4);
    cudaFuncSetAttribute(hmma_gemm_kernel<8>,
                         cudaFuncAttributeMaxDynamicSharedMemorySize, SMEM_W8);
    cudaFuncSetAttribute(cl_hmma_kernel,
                         cudaFuncAttributeMaxDynamicSharedMemorySize, SMEM_W8);
    cudaFuncSetAttribute(cen_hmma_kernel,
                         cudaFuncAttributeMaxDynamicSharedMemorySize, SMEM_W8);

    // 0) prep: coalesced splits + tiled transposes
    cvt_split_kernel<<<2097152 / 1024, 256>>>(x, xh, xl, 2097152);
    cvt_split_kernel<<<6291456 / 1024, 256>>>(mem, memh, meml, 6291456);
    cvt_split5_kernel<<<dim3(256, 5), 256>>>(
        q_w, qwh, qwl, 65536,
        proj_w, pwh, pwl, 65536,
        fc1_w, f1h, f1l, 262144,
        fc2_w, f2h, f2l, 262144,
        cw, cwh, cwl, 38400);
    transpose_split_kernel<<<dim3(128, 8, 2), dim3(32, 8)>>>(x, xth, xtl);
    transpose_split_kernel<<<dim3(128, 8, 6), dim3(32, 8)>>>(mem, memth, memtl);

    // 1) cl (HMMA, pipelined)
    cl_hmma_kernel<<<dim3(32, 2, 8), 256, SMEM_W8>>>(cwh, cwl, xh, xl, memh, meml, cl);
    // 2) prompt cos -> scale vectors only
    prompt_scale_kernel<<<dim3(TNE / 256, 1, BB), 256>>>(z, cl, p1, p2, cz, cc);
    // 3) combine (fp32, scale-on-load) -> cluster_x_z + center
    comb_gemm2_kernel<<<dim3(TNE / 128, 3, BB), 256>>>(tdt1, tdt2, z, cl, cz, cc, cxz, ctr);
    // 4) softmax -> bf16 hi/lo
    softmax_kernel<<<BB * TT4 * NC, 256>>>(cxz, softh, softl);
    // 5) cen (HMMA, split-K atomic, pipelined)
    zero_cen_kernel<<<(307200 + 255) / 256, 256>>>(cen);
    cen_hmma_kernel<<<dim3(2, 2, 64), 256, SMEM_W8>>>(softh, softl, xth, xtl, memth, memtl, cen);
    // 6) gating + LN
    cin_kernel<<<BB * NC, 256>>>(cen, alpha, beta, norm_w, norm_b, cinln);
    // 7) k/v projections
    gemm_tb_kernel<<<dim3(CC / OBN, (BB * NC + OBM - 1) / OBM), 256>>>(
        cinln, k_w, k_b, kb, BB * NC, CC, CC, 1.f);
    gemm_tb_kernel<<<dim3(CC / OBN, (BB * NC + OBM - 1) / OBM), 256>>>(
        cinln, v_w, v_b, vb, BB * NC, CC, CC, 1.f);
    // 8) q projection (HMMA BN=64, pipelined)
    hmma_gemm_kernel<4><<<dim3(4, 64), 256, SMEM_W4>>>(
        xh, xl, qwh, qwl, q_b, qb, CC, CC, 0.17677669529663687f);
    // 9) attention -> bf16 split output
    attn_kernel<<<dim3(N4 / 256, NH, BB), 256>>>(qb, kb, vb, obh, obl);
    // 10) output projection
    hmma_gemm_kernel<4><<<dim3(4, 64), 256, SMEM_W4>>>(
        obh, obl, pwh, pwl, proj_b, oproj, CC, CC, 1.f);
    // 11) out1 = x + LN(oproj), + split
    ln_add_split_kernel<<<BB * N4, 256>>>(x, oproj, norm_w, norm_b, out1, o1h, o1l);
    // 12) fc1 (HMMA BN=128)
    hmma_gemm_kernel<8><<<dim3(8, 64), 256, SMEM_W8>>>(
        o1h, o1l, f1h, f1l, fc1_b, h1, HID, CC, 1.f);
    // 13) depthwise conv + gelu -> split
    dwconv_gelu_bf16_kernel<<<(BB * N4 * HID + 255) / 256, 256>>>(h1, dw_w, dw_b, gh, gl);
    // 14) fc2 (HMMA BN=64)
    hmma_gemm_kernel<4><<<dim3(4, 64), 256, SMEM_W4>>>(
        gh, gl, f2h, f2l, fc2_b, h2, CC, HID, 1.f);
    // 15) out = out1 + LN(h2)
    ln_add_kernel<<<BB * N4, 256>>>(out1, h2, norm_w, norm_b, out0);
}

// round 9
// speedup vs baseline: 1.8472x; 1.1708x over previous
#include <cuda_runtime.h>
#include <cuda_bf16.h>
#include <math.h>
#include <stdint.h>

typedef __nv_bfloat16 bf16;

// ---------------- fixed problem dims ----------------
#define BB   2
#define TT4  4
#define N4   4096
#define CC   256
#define NC   150
#define TNE  16384
#define HID  1024
#define NH   8
#define HD   32
#define HH   64
#define WW   64
#define KPAD 160

#define OUT0_ELEMS 2097152
#define CXZ_ELEMS  4915200

// ---------------- scratch ----------------
__device__ float g_cl[4915200];
__device__ float g_cz[32768], g_cc[32768];
__device__ float g_cen[307200];
__device__ float g_cinln[76800];
__device__ float g_kbuf[76800];
__device__ float g_vbuf[76800];
__device__ float g_q[2097152];
__device__ float g_oproj[2097152];
__device__ float g_out1[2097152];
__device__ float g_h1[8388608];
__device__ float g_h2[2097152];

// bf16 hi/lo split buffers
__device__ bf16 g_xh[2097152],   g_xl[2097152];
__device__ bf16 g_memh[6291456], g_meml[6291456];
__device__ bf16 g_xth[2097152],  g_xtl[2097152];
__device__ bf16 g_memth[6291456], g_memtl[6291456];
__device__ bf16 g_cwh[38400],    g_cwl[38400];
__device__ bf16 g_t1h[25600], g_t1l[25600], g_t2h[25600], g_t2l[25600];
__device__ bf16 g_zth[5242880],  g_ztl[5242880];   // (B, TNE, 160)
__device__ bf16 g_clth[5242880], g_cltl[5242880];  // (B, TNE, 160)
__device__ bf16 g_softh[4915200], g_softl[4915200];
__device__ bf16 g_obh[2097152], g_obl[2097152];
__device__ bf16 g_o1h[2097152], g_o1l[2097152];
__device__ bf16 g_gh[8388608],  g_gl[8388608];
__device__ bf16 g_qwh[65536],  g_qwl[65536];
__device__ bf16 g_pwh[65536],  g_pwl[65536];
__device__ bf16 g_f1h[262144], g_f1l[262144];
__device__ bf16 g_f2h[262144], g_f2l[262144];

// ---------------- warp-level bf16 MMA + cp.async ----------
__device__ __forceinline__ void mma16816(float* d, const uint32_t* a, const uint32_t* b) {
    asm volatile(
        "mma.sync.aligned.m16n8k16.row.col.f32.bf16.bf16.f32 "
        "{%0,%1,%2,%3}, {%4,%5,%6,%7}, {%8,%9}, {%0,%1,%2,%3};\n"
        : "+f"(d[0]), "+f"(d[1]), "+f"(d[2]), "+f"(d[3])
        : "r"(a[0]), "r"(a[1]), "r"(a[2]), "r"(a[3]), "r"(b[0]), "r"(b[1]));
}
__device__ __forceinline__ uint32_t smem_to_u32(const void* p) {
    uint32_t a;
    asm("{ .reg .u64 t; cvta.to.shared.u64 t, %1; cvt.u32.u64 %0, t; }"
        : "=r"(a) : "l"(p));
    return a;
}
__device__ __forceinline__ void cp_async16(uint32_t s, const void* g, bool v) {
    int sz = v ? 16 : 0;
    asm volatile("cp.async.cg.shared.global [%0], [%1], 16, %2;\n"
                 :: "r"(s), "l"(g), "r"(sz));
}
__device__ __forceinline__ void cp_commit() {
    asm volatile("cp.async.commit_group;\n" ::: "memory");
}
template<int N> __device__ __forceinline__ void cp_wait() {
    asm volatile("cp.async.wait_group %0;\n" :: "n"(N) : "memory");
}

#define SAS 40

template<int WNT>
__device__ __forceinline__ void hmma_chunk(
    bf16 (*sAh)[SAS], bf16 (*sAl)[SAS], bf16 (*sBh)[SAS], bf16 (*sBl)[SAS],
    int wm, int wn, int g, int tg, float (*acc)[WNT][4])
{
    #pragma unroll
    for (int ks = 0; ks < 2; ks++) {
        int kc = ks * 16 + tg * 2;
        uint32_t ah[2][4], al[2][4], bh[WNT][2], bl[WNT][2];
        #pragma unroll
        for (int mt = 0; mt < 2; mt++) {
            int r = wm * 32 + mt * 16 + g;
            ah[mt][0] = *(const uint32_t*)&sAh[r][kc];
            ah[mt][1] = *(const uint32_t*)&sAh[r + 8][kc];
            ah[mt][2] = *(const uint32_t*)&sAh[r][kc + 8];
            ah[mt][3] = *(const uint32_t*)&sAh[r + 8][kc + 8];
            al[mt][0] = *(const uint32_t*)&sAl[r][kc];
            al[mt][1] = *(const uint32_t*)&sAl[r + 8][kc];
            al[mt][2] = *(const uint32_t*)&sAl[r][kc + 8];
            al[mt][3] = *(const uint32_t*)&sAl[r + 8][kc + 8];
        }
        #pragma unroll
        for (int nt = 0; nt < WNT; nt++) {
            int nr = wn * (WNT * 8) + nt * 8 + g;
            bh[nt][0] = *(const uint32_t*)&sBh[nr][kc];
            bh[nt][1] = *(const uint32_t*)&sBh[nr][kc + 8];
            bl[nt][0] = *(const uint32_t*)&sBl[nr][kc];
            bl[nt][1] = *(const uint32_t*)&sBl[nr][kc + 8];
        }
        #pragma unroll
        for (int mt = 0; mt < 2; mt++)
            #pragma unroll
            for (int nt = 0; nt < WNT; nt++) {
                mma16816(acc[mt][nt], ah[mt], bh[nt]);
                mma16816(acc[mt][nt], ah[mt], bl[nt]);
                mma16816(acc[mt][nt], al[mt], bh[nt]);
            }
    }
}

// ---- 3-stage cp.async pipelined mainloop ----
template<int WNT, typename F>
__device__ __forceinline__ void hmma_pipe(char* sm, int nk, F getp, float (*acc)[WNT][4])
{
    constexpr int BN = 16 * WNT;
    constexpr int ASZ = 128 * SAS * 2;
    constexpr int BSZ = BN * SAS * 2;
    constexpr int STG = 2 * ASZ + 2 * BSZ;
    int tid = threadIdx.x;
    int wid = tid >> 5, lane = tid & 31;
    int wm = wid & 3, wn = wid >> 2, g = lane >> 2, tg = lane & 3;
    int lrow = tid >> 1, lhalf = (tid & 1) * 16;
    bool bload = (WNT == 8) || (tid < BN * 2);
    uint32_t sb = smem_to_u32(sm);
    uint32_t off = (uint32_t)(lrow * SAS + lhalf) * 2;

    __syncthreads();   // protect stage buffers from prior use

    auto issue = [&](int c) {
        uint32_t st = sb + (c % 3) * STG;
        const bf16 *ah, *al, *bh, *bl; bool av;
        getp(c, ah, al, bh, bl, av);
        cp_async16(st + off, ah, av);
        cp_async16(st + off + 16, ah + 8, av);
        cp_async16(st + ASZ + off, al, av);
        cp_async16(st + ASZ + off + 16, al + 8, av);
        if (bload) {
            cp_async16(st + 2 * ASZ + off, bh, true);
            cp_async16(st + 2 * ASZ + off + 16, bh + 8, true);
            cp_async16(st + 2 * ASZ + BSZ + off, bl, true);
            cp_async16(st + 2 * ASZ + BSZ + off + 16, bl + 8, true);
        }
        cp_commit();
    };

    issue(0); issue(1);
    for (int c = 0; c < nk; c++) {
        if (c + 2 <= nk) cp_wait<1>(); else cp_wait<0>();
        __syncthreads();
        {
            char* st = sm + (c % 3) * STG;
            bf16 (*sAh)[SAS] = (bf16(*)[SAS])st;
            bf16 (*sAl)[SAS] = (bf16(*)[SAS])(st + ASZ);
            bf16 (*sBh)[SAS] = (bf16(*)[SAS])(st + 2 * ASZ);
            bf16 (*sBl)[SAS] = (bf16(*)[SAS])(st + 2 * ASZ + BSZ);
            hmma_chunk<WNT>(sAh, sAl, sBh, sBl, wm, wn, g, tg, acc);
        }
        if (c + 2 < nk) issue(c + 2);
    }
}

// ================= HMMA GEMM (q/proj/fc1/fc2) ============
template<int WNT>
__global__ void __launch_bounds__(256)
hmma_gemm_kernel(const bf16* __restrict__ Ah, const bf16* __restrict__ Al,
                 const bf16* __restrict__ Bh, const bf16* __restrict__ Bl,
                 const float* __restrict__ bias, float* __restrict__ C,
                 int Ntot, int K, float scale)
{
    extern __shared__ char sm[];
    constexpr int BN = 16 * WNT;
    int tid = threadIdx.x, wid = tid >> 5, lane = tid & 31;
    int wm = wid & 3, wn = wid >> 2, g = lane >> 2, tg = lane & 3;
    int m0 = blockIdx.y * 128, n0 = blockIdx.x * BN;
    int lrow = tid >> 1, lhalf = (tid & 1) * 16;

    float acc[2][WNT][4] = {};
    auto getp = [&](int c, const bf16*& ah, const bf16*& al,
                    const bf16*& bh, const bf16*& bl, bool& av) {
        int k0 = (c << 5) + lhalf;
        ah = Ah + (size_t)(m0 + lrow) * K + k0;
        al = Al + (size_t)(m0 + lrow) * K + k0;
        bh = Bh + (size_t)(n0 + lrow) * K + k0;
        bl = Bl + (size_t)(n0 + lrow) * K + k0;
        av = true;
    };
    hmma_pipe<WNT>(sm, K >> 5, getp, acc);

    #pragma unroll
    for (int mt = 0; mt < 2; mt++) {
        int r0 = m0 + wm * 32 + mt * 16 + g;
        #pragma unroll
        for (int nt = 0; nt < WNT; nt++) {
            int col = n0 + wn * (WNT * 8) + nt * 8 + tg * 2;
            float b0 = bias[col], b1 = bias[col + 1];
            float2 v0, v1;
            v0.x = (acc[mt][nt][0] + b0) * scale;
            v0.y = (acc[mt][nt][1] + b1) * scale;
            v1.x = (acc[mt][nt][2] + b0) * scale;
            v1.y = (acc[mt][nt][3] + b1) * scale;
            *(float2*)&C[(size_t)r0 * Ntot + col] = v0;
            *(float2*)&C[(size_t)(r0 + 8) * Ntot + col] = v1;
        }
    }
}

// ================= cl HMMA =================
__global__ void __launch_bounds__(256)
cl_hmma_kernel(const bf16* __restrict__ cwh, const bf16* __restrict__ cwl,
               const bf16* __restrict__ xh, const bf16* __restrict__ xl,
               const bf16* __restrict__ memh, const bf16* __restrict__ meml,
               float* __restrict__ cl)
{
    extern __shared__ char sm[];
    int bt = blockIdx.z, b = bt >> 2, t = bt & 3;
    const bf16* Bh = (t < 3) ? memh + (size_t)(b * 3 + t) * 1048576 : xh + (size_t)b * 1048576;
    const bf16* Bl = (t < 3) ? meml + (size_t)(b * 3 + t) * 1048576 : xl + (size_t)b * 1048576;
    float* Cp = cl + (size_t)bt * 614400;

    int tid = threadIdx.x, wid = tid >> 5, lane = tid & 31;
    int wm = wid & 3, wn = wid >> 2, g = lane >> 2, tg = lane & 3;
    int m0 = blockIdx.y * 128, n0 = blockIdx.x * 128;
    int lrow = tid >> 1, lhalf = (tid & 1) * 16;
    bool aval = (m0 + lrow) < NC;

    float acc[2][8][4] = {};
    auto getp = [&](int c, const bf16*& ah, const bf16*& al,
                    const bf16*& bh, const bf16*& bl, bool& av) {
        int k0 = (c << 5) + lhalf;
        ah = cwh + (size_t)(m0 + lrow) * CC + k0;
        al = cwl + (size_t)(m0 + lrow) * CC + k0;
        bh = Bh + (size_t)(n0 + lrow) * CC + k0;
        bl = Bl + (size_t)(n0 + lrow) * CC + k0;
        av = aval;
    };
    hmma_pipe<8>(sm, 8, getp, acc);

    #pragma unroll
    for (int mt = 0; mt < 2; mt++) {
        int r0 = m0 + wm * 32 + mt * 16 + g;
        #pragma unroll
        for (int nt = 0; nt < 8; nt++) {
            int col = n0 + wn * 64 + nt * 8 + tg * 2;
            if (r0 < NC)
                *(float2*)&Cp[(size_t)r0 * N4 + col] = make_float2(acc[mt][nt][0], acc[mt][nt][1]);
            if (r0 + 8 < NC)
                *(float2*)&Cp[(size_t)(r0 + 8) * N4 + col] = make_float2(acc[mt][nt][2], acc[mt][nt][3]);
        }
    }
}

// ================= comb HMMA: cxz[j,m] = cz[m]*(T1^T z)[j,m] + cc[m]*(T2^T cl)[j,m]
// A = tdt^T padded (160x160); B = zT/clT (B, TNE, 160). BN=64, K=160 (5 chunks).
__global__ void __launch_bounds__(256)
comb_hmma_kernel(const bf16* __restrict__ t1h, const bf16* __restrict__ t1l,
                 const bf16* __restrict__ t2h, const bf16* __restrict__ t2l,
                 const bf16* __restrict__ zth, const bf16* __restrict__ ztl,
                 const bf16* __restrict__ clth, const bf16* __restrict__ cltl,
                 const float* __restrict__ cz, const float* __restrict__ cc,
                 float* __restrict__ cxz, float* __restrict__ ctr)
{
    extern __shared__ char sm[];
    int b = blockIdx.z;
    int j0 = blockIdx.y * 128, n0 = blockIdx.x * 64;
    int tid = threadIdx.x, wid = tid >> 5, lane = tid & 31;
    int wm = wid & 3, wn = wid >> 2, g = lane >> 2, tg = lane & 3;
    int lrow = tid >> 1, lhalf = (tid & 1) * 16;
    bool aval = (j0 + lrow) < KPAD;

    float acc1[2][4][4] = {}, acc2[2][4][4] = {};
    const bf16* Bz_h = zth + (size_t)b * TNE * KPAD;
    const bf16* Bz_l = ztl + (size_t)b * TNE * KPAD;
    const bf16* Bc_h = clth + (size_t)b * TNE * KPAD;
    const bf16* Bc_l = cltl + (size_t)b * TNE * KPAD;

    auto getp1 = [&](int c, const bf16*& ah, const bf16*& al,
                     const bf16*& bh, const bf16*& bl, bool& av) {
        int k0 = (c << 5) + lhalf;
        ah = t1h + (size_t)(j0 + lrow) * KPAD + k0;
        al = t1l + (size_t)(j0 + lrow) * KPAD + k0;
        bh = Bz_h + (size_t)(n0 + lrow) * KPAD + k0;
        bl = Bz_l + (size_t)(n0 + lrow) * KPAD + k0;
        av = aval;
    };
    hmma_pipe<4>(sm, 5, getp1, acc1);
    auto getp2 = [&](int c, const bf16*& ah, const bf16*& al,
                     const bf16*& bh, const bf16*& bl, bool& av) {
        int k0 = (c << 5) + lhalf;
        ah = t2h + (size_t)(j0 + lrow) * KPAD + k0;
        al = t2l + (size_t)(j0 + lrow) * KPAD + k0;
        bh = Bc_h + (size_t)(n0 + lrow) * KPAD + k0;
        bl = Bc_l + (size_t)(n0 + lrow) * KPAD + k0;
        av = aval;
    };
    hmma_pipe<4>(sm, 5, getp2, acc2);

    #pragma unroll
    for (int mt = 0; mt < 2; mt++) {
        int r0 = j0 + wm * 32 + mt * 16 + g;
        #pragma unroll
        for (int nt = 0; nt < 4; nt++) {
            int col = n0 + wn * 32 + nt * 8 + tg * 2;
            float s0z = cz[(size_t)b * TNE + col],     s1z = cz[(size_t)b * TNE + col + 1];
            float s0c = cc[(size_t)b * TNE + col],     s1c = cc[(size_t)b * TNE + col + 1];
            int t = col >> 12, n = col & 4095;
            if (r0 < NC) {
                float2 v;
                v.x = s0z * acc1[mt][nt][0] + s0c * acc2[mt][nt][0];
                v.y = s1z * acc1[mt][nt][1] + s1c * acc2[mt][nt][1];
                *(float2*)&cxz[((size_t)b * NC + r0) * TNE + col] = v;
                *(float2*)&ctr[((size_t)(b * TT4 + t) * NC + r0) * N4 + n] = v;
            }
            if (r0 + 8 < NC) {
                float2 v;
                v.x = s0z * acc1[mt][nt][2] + s0c * acc2[mt][nt][2];
                v.y = s1z * acc1[mt][nt][3] + s1c * acc2[mt][nt][3];
                *(float2*)&cxz[((size_t)b * NC + r0 + 8) * TNE + col] = v;
                *(float2*)&ctr[((size_t)(b * TT4 + t) * NC + r0 + 8) * N4 + n] = v;
            }
        }
    }
}

// ================= cen HMMA (split-K, atomic) =================
__global__ void __launch_bounds__(256)
cen_hmma_kernel(const bf16* __restrict__ softh, const bf16* __restrict__ softl,
                const bf16* __restrict__ xth, const bf16* __restrict__ xtl,
                const bf16* __restrict__ memth, const bf16* __restrict__ memtl,
                float* __restrict__ cen)
{
    extern __shared__ char sm[];
    int bt = blockIdx.z >> 3, sp = blockIdx.z & 7;
    int b = bt >> 2, t = bt & 3;
    const bf16* Ah = softh + (size_t)bt * 614400;
    const bf16* Al = softl + (size_t)bt * 614400;
    const bf16* Bh = (t < 3) ? memth + (size_t)(b * 3 + t) * 1048576 : xth + (size_t)b * 1048576;
    const bf16* Bl = (t < 3) ? memtl + (size_t)(b * 3 + t) * 1048576 : xtl + (size_t)b * 1048576;
    float* Cp = cen + (size_t)bt * 38400;
    int koff = sp * 512;

    int tid = threadIdx.x, wid = tid >> 5, lane = tid & 31;
    int wm = wid & 3, wn = wid >> 2, g = lane >> 2, tg = lane & 3;
    int m0 = blockIdx.y * 128, n0 = blockIdx.x * 128;
    int lrow = tid >> 1, lhalf = (tid & 1) * 16;
    bool aval = (m0 + lrow) < NC;

    float acc[2][8][4] = {};
    auto getp = [&](int c, const bf16*& ah, const bf16*& al,
                    const bf16*& bh, const bf16*& bl, bool& av) {
        int k0 = koff + (c << 5) + lhalf;
        ah = Ah + (size_t)(m0 + lrow) * N4 + k0;
        al = Al + (size_t)(m0 + lrow) * N4 + k0;
        bh = Bh + (size_t)(n0 + lrow) * N4 + k0;
        bl = Bl + (size_t)(n0 + lrow) * N4 + k0;
        av = aval;
    };
    hmma_pipe<8>(sm, 16, getp, acc);

    #pragma unroll
    for (int mt = 0; mt < 2; mt++) {
        int r0 = m0 + wm * 32 + mt * 16 + g;
        #pragma unroll
        for (int nt = 0; nt < 8; nt++) {
            int col = n0 + wn * 64 + nt * 8 + tg * 2;
            if (r0 < NC) {
                atomicAdd(&Cp[(size_t)r0 * CC + col], acc[mt][nt][0]);
                atomicAdd(&Cp[(size_t)r0 * CC + col + 1], acc[mt][nt][1]);
            }
            if (r0 + 8 < NC) {
                atomicAdd(&Cp[(size_t)(r0 + 8) * CC + col], acc[mt][nt][2]);
                atomicAdd(&Cp[(size_t)(r0 + 8) * CC + col + 1], acc[mt][nt][3]);
            }
        }
    }
}

// ---------------- splits ----------------
__device__ __forceinline__ void split_store4(const float4 v, bf16* hi, bf16* lo, int i) {
    bf16 h0 = __float2bfloat16(v.x), h1 = __float2bfloat16(v.y);
    bf16 h2 = __float2bfloat16(v.z), h3 = __float2bfloat16(v.w);
    *(__nv_bfloat162*)(hi + i)     = __nv_bfloat162(h0, h1);
    *(__nv_bfloat162*)(hi + i + 2) = __nv_bfloat162(h2, h3);
    *(__nv_bfloat162*)(lo + i) = __nv_bfloat162(
        __float2bfloat16(v.x - __bfloat162float(h0)),
        __float2bfloat16(v.y - __bfloat162float(h1)));
    *(__nv_bfloat162*)(lo + i + 2) = __nv_bfloat162(
        __float2bfloat16(v.z - __bfloat162float(h2)),
        __float2bfloat16(v.w - __bfloat162float(h3)));
}
__global__ void cvt_split5_kernel(
    const float* a0, bf16* h0, bf16* l0, int s0,
    const float* a1, bf16* h1, bf16* l1, int s1,
    const float* a2, bf16* h2, bf16* l2, int s2,
    const float* a3, bf16* h3, bf16* l3, int s3,
    const float* a4, bf16* h4, bf16* l4, int s4)
{
    const float* in; bf16 *hi, *lo; int n;
    switch (blockIdx.y) {
        case 0: in = a0; hi = h0; lo = l0; n = s0; break;
        case 1: in = a1; hi = h1; lo = l1; n = s1; break;
        case 2: in = a2; hi = h2; lo = l2; n = s2; break;
        case 3: in = a3; hi = h3; lo = l3; n = s3; break;
        default: in = a4; hi = h4; lo = l4; n = s4; break;
    }
    int i = (blockIdx.x * 256 + threadIdx.x) * 4;
    if (i >= n) return;
    split_store4(*(const float4*)(in + i), hi, lo, i);
}

// ---- split + transpose-split in one pass: (4096,256) -> both layouts ----
__global__ void split_all_kernel(const float* __restrict__ in,
                                 bf16* __restrict__ oh, bf16* __restrict__ ol,
                                 bf16* __restrict__ toh, bf16* __restrict__ tol)
{
    __shared__ float tile[32][33];
    const float* src = in + (size_t)blockIdx.z * 1048576;
    bf16* doh = oh + (size_t)blockIdx.z * 1048576;
    bf16* dol = ol + (size_t)blockIdx.z * 1048576;
    bf16* dth = toh + (size_t)blockIdx.z * 1048576;
    bf16* dtl = tol + (size_t)blockIdx.z * 1048576;
    int tx = threadIdx.x, ty = threadIdx.y;
    int r0 = blockIdx.x * 32, c0 = blockIdx.y * 32;
    #pragma unroll
    for (int i = 0; i < 4; i++) {
        int r = r0 + ty + i * 8;
        float v = src[(size_t)r * CC + c0 + tx];
        tile[ty + i * 8][tx] = v;
        bf16 h = __float2bfloat16(v);
        doh[(size_t)r * CC + c0 + tx] = h;
        dol[(size_t)r * CC + c0 + tx] = __float2bfloat16(v - __bfloat162float(h));
    }
    __syncthreads();
    #pragma unroll
    for (int i = 0; i < 4; i++) {
        int c = c0 + ty + i * 8;
        float v = tile[tx][ty + i * 8];
        bf16 h = __float2bfloat16(v);
        dth[(size_t)c * N4 + r0 + tx] = h;
        dtl[(size_t)c * N4 + r0 + tx] = __float2bfloat16(v - __bfloat162float(h));
    }
}

// ---- zT: z (B, NC, TNE) -> (B, TNE, 160) hi/lo, k padded ----
__global__ void zT_split_kernel(const float* __restrict__ z,
                                bf16* __restrict__ oh, bf16* __restrict__ ol)
{
    __shared__ float tile[32][33];
    int b = blockIdx.z;
    int m0 = blockIdx.x * 32, k0 = blockIdx.y * 32;
    int tx = threadIdx.x, ty = threadIdx.y;
    #pragma unroll
    for (int i = 0; i < 4; i++) {
        int k = k0 + ty + i * 8;
        tile[ty + i * 8][tx] = (k < NC) ? z[((size_t)b * NC + k) * TNE + m0 + tx] : 0.f;
    }
    __syncthreads();
    #pragma unroll
    for (int i = 0; i < 4; i++) {
        int m = m0 + ty + i * 8;
        float v = tile[tx][ty + i * 8];
        bf16 h = __float2bfloat16(v);
        size_t idx = ((size_t)b * TNE + m) * KPAD + k0 + tx;
        oh[idx] = h;
        ol[idx] = __float2bfloat16(v - __bfloat162float(h));
    }
}

// ---- clT: cl (bt, k, n) -> (B, t*N4+n, 160) hi/lo ----
__global__ void clT_split_kernel(const float* __restrict__ cl,
                                 bf16* __restrict__ oh, bf16* __restrict__ ol)
{
    __shared__ float tile[32][33];
    int bt = blockIdx.z, b = bt >> 2, t = bt & 3;
    int n0 = blockIdx.x * 32, k0 = blockIdx.y * 32;
    int tx = threadIdx.x, ty = threadIdx.y;
    const float* src = cl + (size_t)bt * 614400;
    #pragma unroll
    for (int i = 0; i < 4; i++) {
        int k = k0 + ty + i * 8;
        tile[ty + i * 8][tx] = (k < NC) ? src[(size_t)k * N4 + n0 + tx] : 0.f;
    }
    __syncthreads();
    #pragma unroll
    for (int i = 0; i < 4; i++) {
        int n = n0 + ty + i * 8;
        float v = tile[tx][ty + i * 8];
        bf16 h = __float2bfloat16(v);
        size_t idx = ((size_t)b * TNE + t * N4 + n) * KPAD + k0 + tx;
        oh[idx] = h;
        ol[idx] = __float2bfloat16(v - __bfloat162float(h));
    }
}

// ---- tdt^T padded split ----
__global__ void tdt_prep_kernel(const float* __restrict__ tdt1, const float* __restrict__ tdt2,
                                bf16* __restrict__ t1h, bf16* __restrict__ t1l,
                                bf16* __restrict__ t2h, bf16* __restrict__ t2l)
{
    int i = blockIdx.x * 256 + threadIdx.x;
    if (i >= KPAD * KPAD) return;
    int j = i / KPAD, k = i % KPAD;
    float v1 = (j < NC && k < NC) ? tdt1[k * NC + j] : 0.f;
    float v2 = (j < NC && k < NC) ? tdt2[k * NC + j] : 0.f;
    bf16 h1 = __float2bfloat16(v1), h2 = __float2bfloat16(v2);
    t1h[i] = h1; t1l[i] = __float2bfloat16(v1 - __bfloat162float(h1));
    t2h[i] = h2; t2l[i] = __float2bfloat16(v2 - __bfloat162float(h2));
}

// ---------------- helpers ----------------
__device__ __forceinline__ float block_reduce_sum(float v, float* sbuf) {
    int tid = threadIdx.x;
    sbuf[tid] = v; __syncthreads();
    for (int s = blockDim.x >> 1; s > 0; s >>= 1) {
        if (tid < s) sbuf[tid] += sbuf[tid + s];
        __syncthreads();
    }
    float r = sbuf[0]; __syncthreads();
    return r;
}
__device__ __forceinline__ float block_reduce_max(float v, float* sbuf) {
    int tid = threadIdx.x;
    sbuf[tid] = v; __syncthreads();
    for (int s = blockDim.x >> 1; s > 0; s >>= 1) {
        if (tid < s) sbuf[tid] = fmaxf(sbuf[tid], sbuf[tid + s]);
        __syncthreads();
    }
    float r = sbuf[0]; __syncthreads();
    return r;
}

// ======== merged k/v projection (fp32, tiny) ====
#define OBM 64
#define OBN 64
#define OBK 16
__global__ void gemm_kv_kernel(const float* __restrict__ A,
                               const float* __restrict__ k_w, const float* __restrict__ k_b,
                               const float* __restrict__ v_w, const float* __restrict__ v_b,
                               float* __restrict__ kout, float* __restrict__ vout)
{
    const float* B = blockIdx.z ? v_w : k_w;
    const float* bias = blockIdx.z ? v_b : k_b;
    float* C = blockIdx.z ? vout : kout;
    const int M = BB * NC;
    __shared__ float As[OBK][OBM];
    __shared__ float Bs[OBK][OBN];
    int tid = threadIdx.x;
    int tx = tid & 15, ty = tid >> 4;
    int m0 = blockIdx.y * OBM, n0 = blockIdx.x * OBN;
    float acc[4][4] = {};
    for (int k0 = 0; k0 < CC; k0 += OBK) {
        #pragma unroll
        for (int j = 0; j < 4; j++) {
            int idx = tid + j * 256;
            int ml = idx / OBK, kl = idx % OBK;
            int m = m0 + ml;
            As[kl][ml] = (m < M) ? A[(size_t)m * CC + k0 + kl] : 0.f;
        }
        #pragma unroll
        for (int j = 0; j < 4; j++) {
            int idx = tid + j * 256;
            int nl = idx / OBK, kl = idx % OBK;
            Bs[kl][nl] = B[(size_t)(n0 + nl) * CC + k0 + kl];
        }
        __syncthreads();
        #pragma unroll
        for (int kk = 0; kk < OBK; kk++) {
            float a[4], b[4];
            *(float4*)a = *(const float4*)&As[kk][ty * 4];
            *(float4*)b = *(const float4*)&Bs[kk][tx * 4];
            #pragma unroll
            for (int i = 0; i < 4; i++)
                #pragma unroll
                for (int j = 0; j < 4; j++)
                    acc[i][j] += a[i] * b[j];
        }
        __syncthreads();
    }
    #pragma unroll
    for (int i = 0; i < 4; i++) {
        int m = m0 + ty * 4 + i;
        if (m >= M) continue;
        #pragma unroll
        for (int j = 0; j < 4; j++) {
            int n = n0 + tx * 4 + j;
            C[(size_t)m * CC + n] = acc[i][j] + bias[n];
        }
    }
}

// ---- prompt cos -> cz/cc scale vectors ----
__global__ void prompt_scale_kernel(const float* __restrict__ z,
                                    const float* __restrict__ cl,
                                    const float* __restrict__ p1,
                                    const float* __restrict__ p2,
                                    float* __restrict__ cz,
                                    float* __restrict__ cc)
{
    int m = blockIdx.x * blockDim.x + threadIdx.x;
    int b = blockIdx.z;
    if (m >= TNE) return;
    int t = m >> 12, n = m & 4095;
    const float* zrow = z + (size_t)b * NC * TNE + m;
    const float* crow = cl + ((size_t)(b * TT4 + t) * NC) * N4 + n;
    float dz = 0, nz = 0, dc = 0, ncs = 0, p1n = 0, p2n = 0;
    for (int k = 0; k < NC; k++) {
        float zv = zrow[(size_t)k * TNE];
        float cv = crow[(size_t)k * N4];
        float a = p1[k], bb = p2[k];
        dz += zv * a; nz += zv * zv; p1n += a * a;
        dc += cv * bb; ncs += cv * cv; p2n += bb * bb;
    }
    float vz = dz / (fmaxf(sqrtf(nz), 1e-12f) * fmaxf(sqrtf(p1n), 1e-12f));
    float vc = dc / (fmaxf(sqrtf(ncs), 1e-12f) * fmaxf(sqrtf(p2n), 1e-12f));
    cz[(size_t)b * TNE + m] = fminf(fmaxf(vz, 0.f), 1.f) * 0.5f;
    cc[(size_t)b * TNE + m] = fminf(fmaxf(vc, 0.f), 1.f) * 0.5f;
}

// ---- softmax -> bf16 hi/lo ----
__global__ void softmax_kernel(const float* __restrict__ cxz,
                               bf16* __restrict__ softh, bf16* __restrict__ softl)
{
    __shared__ float sbuf[256];
    int r = blockIdx.x;
    int k = r % NC;
    int bt = r / NC;
    int b = bt / TT4, t = bt % TT4;
    const float* src = cxz + ((size_t)b * NC + k) * TNE + t * N4;
    bf16* dh = softh + (size_t)r * N4;
    bf16* dl = softl + (size_t)r * N4;
    int tid = threadIdx.x;
    float mx = -3.4e38f;
    for (int i = tid; i < N4; i += 256) mx = fmaxf(mx, src[i]);
    mx = block_reduce_max(mx, sbuf);
    float s = 0.f;
    float ev[16];
    #pragma unroll
    for (int j = 0; j < 16; j++) {
        int i = tid + j * 256;
        ev[j] = expf(src[i] - mx);
        s += ev[j];
    }
    s = block_reduce_sum(s, sbuf);
    float inv = 1.f / s;
    #pragma unroll
    for (int j = 0; j < 16; j++) {
        int i = tid + j * 256;
        float v = ev[j] * inv;
        bf16 h = __float2bfloat16(v);
        dh[i] = h;
        dl[i] = __float2bfloat16(v - __bfloat162float(h));
    }
}

// ---- zero cen ----
__global__ void zero_cen_kernel(float* __restrict__ cen)
{
    int i = blockIdx.x * blockDim.x + threadIdx.x;
    if (i < 307200) cen[i] = 0.f;
}

// ---- C_in gating + LayerNorm ----
__global__ void cin_kernel(const float* __restrict__ cen,
                           const float* __restrict__ alpha,
                           const float* __restrict__ beta,
                           const float* __restrict__ nw,
                           const float* __restrict__ nb,
                           float* __restrict__ cinln)
{
    __shared__ float sbuf[256];
    int bk = blockIdx.x;
    int b = bk / NC, k = bk % NC;
    int c = threadIdx.x;
    float last = cen[((size_t)(b * TT4 + 3) * NC + k) * CC + c];
    float pv[3];
    #pragma unroll
    for (int t = 0; t < 3; t++)
        pv[t] = cen[((size_t)(b * TT4 + t) * NC + k) * CC + c];
    float nl = block_reduce_sum(last * last, sbuf);
    float al = alpha[0], be = beta[0];
    float g[3];
    #pragma unroll
    for (int t = 0; t < 3; t++) {
        float dt = block_reduce_sum(last * pv[t], sbuf);
        float np = block_reduce_sum(pv[t] * pv[t], sbuf);
        float denom = fmaxf(sqrtf(nl) * sqrtf(np), 1e-8f);
        g[t] = 1.f / (1.f + expf(-(be + al * dt / denom)));
    }
    float cin = last + g[0] * pv[0] + g[1] * pv[1] + g[2] * pv[2];
    float mean = block_reduce_sum(cin, sbuf) * (1.f / CC);
    float d = cin - mean;
    float var = block_reduce_sum(d * d, sbuf) * (1.f / CC);
    cinln[((size_t)b * NC + k) * CC + c] = d * rsqrtf(var + 1e-5f) * nw[c] + nb[c];
}

// ---- attention -> bf16 hi/lo output ----
__global__ void attn_kernel(const float* __restrict__ q,
                            const float* __restrict__ kbuf,
                            const float* __restrict__ vbuf,
                            bf16* __restrict__ obh, bf16* __restrict__ obl)
{
    __shared__ float kh[NC * 33];
    __shared__ float vh[NC * 33];
    int b = blockIdx.z, h = blockIdx.y;
    int tid = threadIdx.x;
    int warp = tid >> 5, lane = tid & 31;
    for (int idx = tid; idx < NC * HD; idx += blockDim.x) {
        int kk = idx / HD, d = idx % HD;
        kh[kk * 33 + d] = kbuf[((size_t)b * NC + kk) * CC + h * HD + d];
        vh[kk * 33 + d] = vbuf[((size_t)b * NC + kk) * CC + h * HD + d];
    }
    __syncthreads();
    const unsigned FULL = 0xffffffffu;
    for (int ni = warp; ni < 256; ni += 8) {
        int n = blockIdx.x * 256 + ni;
        float qv = q[((size_t)b * N4 + n) * CC + h * HD + lane];
        float lg[5];
        #pragma unroll
        for (int i = 0; i < 5; i++) {
            int kk = lane + 32 * i;
            int kks = (kk < NC) ? kk : (NC - 1);
            float acc = 0.f;
            #pragma unroll
            for (int d = 0; d < 32; d++) {
                float qd = __shfl_sync(FULL, qv, d);
                acc += qd * kh[kks * 33 + d];
            }
            lg[i] = (kk < NC) ? acc : -3.4e38f;
        }
        float mx = lg[0];
        #pragma unroll
        for (int i = 1; i < 5; i++) mx = fmaxf(mx, lg[i]);
        #pragma unroll
        for (int off = 16; off > 0; off >>= 1)
            mx = fmaxf(mx, __shfl_xor_sync(FULL, mx, off));
        float p[5], s = 0.f;
        #pragma unroll
        for (int i = 0; i < 5; i++) { p[i] = expf(lg[i] - mx); s += p[i]; }
        #pragma unroll
        for (int off = 16; off > 0; off >>= 1)
            s += __shfl_xor_sync(FULL, s, off);
        float inv = 1.f / s;
        float od = 0.f;
        #pragma unroll
        for (int i = 0; i < 5; i++) {
            float pi = p[i] * inv;
            #pragma unroll
            for (int l = 0; l < 32; l++) {
                float a = __shfl_sync(FULL, pi, l);
                int kk = l + 32 * i;
                if (kk < NC) od += a * vh[kk * 33 + lane];
            }
        }
        size_t idx = ((size_t)b * N4 + n) * CC + h * HD + lane;
        bf16 hh = __float2bfloat16(od);
        obh[idx] = hh;
        obl[idx] = __float2bfloat16(od - __bfloat162float(hh));
    }
}

// ---- out = base + LN(xin) ----
__global__ void ln_add_kernel(const float* __restrict__ base,
                              const float* __restrict__ xin,
                              const float* __restrict__ nw,
                              const float* __restrict__ nb,
                              float* __restrict__ out)
{
    __shared__ float sbuf[256];
    size_t row = blockIdx.x;
    int c = threadIdx.x;
    float v = xin[row * CC + c];
    float mean = block_reduce_sum(v, sbuf) * (1.f / CC);
    float d = v - mean;
    float var = block_reduce_sum(d * d, sbuf) * (1.f / CC);
    out[row * CC + c] = base[row * CC + c] + d * rsqrtf(var + 1e-5f) * nw[c] + nb[c];
}

// ---- out = base + LN(xin), + bf16 split ----
__global__ void ln_add_split_kernel(const float* __restrict__ base,
                                    const float* __restrict__ xin,
                                    const float* __restrict__ nw,
                                    const float* __restrict__ nb,
                                    float* __restrict__ out,
                                    bf16* __restrict__ ohi, bf16* __restrict__ olo)
{
    __shared__ float sbuf[256];
    size_t row = blockIdx.x;
    int c = threadIdx.x;
    float v = xin[row * CC + c];
    float mean = block_reduce_sum(v, sbuf) * (1.f / CC);
    float d = v - mean;
    float var = block_reduce_sum(d * d, sbuf) * (1.f / CC);
    float r = base[row * CC + c] + d * rsqrtf(var + 1e-5f) * nw[c] + nb[c];
    size_t idx = row * CC + c;
    out[idx] = r;
    bf16 h = __float2bfloat16(r);
    ohi[idx] = h;
    olo[idx] = __float2bfloat16(r - __bfloat162float(h));
}

// ---- depthwise conv + GELU -> bf16 hi/lo ----
__global__ void dwconv_gelu_bf16_kernel(const float* __restrict__ h1,
                                        const float* __restrict__ dw_w,
                                        const float* __restrict__ dw_b,
                                        bf16* __restrict__ gh, bf16* __restrict__ gl)
{
    int idx = blockIdx.x * blockDim.x + threadIdx.x;
    if (idx >= BB * N4 * HID) return;
    int ch = idx & (HID - 1);
    int r = idx >> 10;
    int n = r & (N4 - 1);
    int b = r >> 12;
    int y = n >> 6, x = n & 63;
    float acc = dw_b[ch];
    #pragma unroll
    for (int dy = 0; dy < 3; dy++) {
        int yy = y + dy - 1;
        if (yy < 0 || yy >= HH) continue;
        #pragma unroll
        for (int dx = 0; dx < 3; dx++) {
            int xx = x + dx - 1;
            if (xx < 0 || xx >= WW) continue;
            acc += h1[((size_t)b * N4 + yy * WW + xx) * HID + ch] *
                   dw_w[ch * 9 + dy * 3 + dx];
        }
    }
    float v = 0.5f * acc * (1.0f + erff(acc * 0.70710678118654752f));
    bf16 h = __float2bfloat16(v);
    gh[idx] = h;
    gl[idx] = __float2bfloat16(v - __bfloat162float(h));
}

// ================= host launcher =================
#define SMEM_W4  92160
#define SMEM_W8  122880

extern "C" void kernel_launch(void* const* d_in, const int* in_sizes, int n_in,
                              void* d_out, int out_size)
{
    const float* x      = (const float*)d_in[0];
    const float* z      = (const float*)d_in[1];
    const float* mem    = (const float*)d_in[2];
    const float* cw     = (const float*)d_in[3];
    const float* p1     = (const float*)d_in[4];
    const float* tdt1   = (const float*)d_in[5];
    const float* p2     = (const float*)d_in[6];
    const float* tdt2   = (const float*)d_in[7];
    const float* alpha  = (const float*)d_in[8];
    const float* beta   = (const float*)d_in[9];
    const float* q_w    = (const float*)d_in[10];
    const float* q_b    = (const float*)d_in[11];
    const float* k_w    = (const float*)d_in[12];
    const float* k_b    = (const float*)d_in[13];
    const float* v_w    = (const float*)d_in[14];
    const float* v_b    = (const float*)d_in[15];
    const float* proj_w = (const float*)d_in[16];
    const float* proj_b = (const float*)d_in[17];
    const float* norm_w = (const float*)d_in[18];
    const float* norm_b = (const float*)d_in[19];
    const float* fc1_w  = (const float*)d_in[20];
    const float* fc1_b  = (const float*)d_in[21];
    const float* dw_w   = (const float*)d_in[22];
    const float* dw_b   = (const float*)d_in[23];
    const float* fc2_w  = (const float*)d_in[24];
    const float* fc2_b  = (const float*)d_in[25];

    float* out0 = (float*)d_out;
    float* cxz  = out0 + OUT0_ELEMS;
    float* ctr  = out0 + OUT0_ELEMS + CXZ_ELEMS;

    float *cl, *cz, *cc, *cen, *cinln, *kb, *vb, *qb, *oproj, *out1, *h1, *h2;
    bf16 *xh, *xl, *memh, *meml, *xth, *xtl, *memth, *memtl, *cwh, *cwl;
    bf16 *t1h, *t1l, *t2h, *t2l, *zth, *ztl, *clth, *cltl;
    bf16 *softh, *softl, *obh, *obl, *o1h, *o1l, *gh, *gl;
    bf16 *qwh, *qwl, *pwh, *pwl, *f1h, *f1l, *f2h, *f2l;
    cudaGetSymbolAddress((void**)&cl,    g_cl);
    cudaGetSymbolAddress((void**)&cz,    g_cz);
    cudaGetSymbolAddress((void**)&cc,    g_cc);
    cudaGetSymbolAddress((void**)&cen,   g_cen);
    cudaGetSymbolAddress((void**)&cinln, g_cinln);
    cudaGetSymbolAddress((void**)&kb,    g_kbuf);
    cudaGetSymbolAddress((void**)&vb,    g_vbuf);
    cudaGetSymbolAddress((void**)&qb,    g_q);
    cudaGetSymbolAddress((void**)&oproj, g_oproj);
    cudaGetSymbolAddress((void**)&out1,  g_out1);
    cudaGetSymbolAddress((void**)&h1,    g_h1);
    cudaGetSymbolAddress((void**)&h2,    g_h2);
    cudaGetSymbolAddress((void**)&xh,   g_xh);   cudaGetSymbolAddress((void**)&xl,   g_xl);
    cudaGetSymbolAddress((void**)&memh, g_memh); cudaGetSymbolAddress((void**)&meml, g_meml);
    cudaGetSymbolAddress((void**)&xth,  g_xth);  cudaGetSymbolAddress((void**)&xtl,  g_xtl);
    cudaGetSymbolAddress((void**)&memth, g_memth); cudaGetSymbolAddress((void**)&memtl, g_memtl);
    cudaGetSymbolAddress((void**)&cwh,  g_cwh);  cudaGetSymbolAddress((void**)&cwl,  g_cwl);
    cudaGetSymbolAddress((void**)&t1h,  g_t1h);  cudaGetSymbolAddress((void**)&t1l,  g_t1l);
    cudaGetSymbolAddress((void**)&t2h,  g_t2h);  cudaGetSymbolAddress((void**)&t2l,  g_t2l);
    cudaGetSymbolAddress((void**)&zth,  g_zth);  cudaGetSymbolAddress((void**)&ztl,  g_ztl);
    cudaGetSymbolAddress((void**)&clth, g_clth); cudaGetSymbolAddress((void**)&cltl, g_cltl);
    cudaGetSymbolAddress((void**)&softh, g_softh); cudaGetSymbolAddress((void**)&softl, g_softl);
    cudaGetSymbolAddress((void**)&obh, g_obh); cudaGetSymbolAddress((void**)&obl, g_obl);
    cudaGetSymbolAddress((void**)&o1h, g_o1h); cudaGetSymbolAddress((void**)&o1l, g_o1l);
    cudaGetSymbolAddress((void**)&gh,  g_gh);  cudaGetSymbolAddress((void**)&gl,  g_gl);
    cudaGetSymbolAddress((void**)&qwh, g_qwh); cudaGetSymbolAddress((void**)&qwl, g_qwl);
    cudaGetSymbolAddress((void**)&pwh, g_pwh); cudaGetSymbolAddress((void**)&pwl, g_pwl);
    cudaGetSymbolAddress((void**)&f1h, g_f1h); cudaGetSymbolAddress((void**)&f1l, g_f1l);
    cudaGetSymbolAddress((void**)&f2h, g_f2h); cudaGetSymbolAddress((void**)&f2l, g_f2l);

    cudaFuncSetAttribute(hmma_gemm_kernel<4>,
                         cudaFuncAttributeMaxDynamicSharedMemorySize, SMEM_W4);
    cudaFuncSetAttribute(hmma_gemm_kernel<8>,
                         cudaFuncAttributeMaxDynamicSharedMemorySize, SMEM_W8);
    cudaFuncSetAttribute(cl_hmma_kernel,
                         cudaFuncAttributeMaxDynamicSharedMemorySize, SMEM_W8);
    cudaFuncSetAttribute(cen_hmma_kernel,
                         cudaFuncAttributeMaxDynamicSharedMemorySize, SMEM_W8);
    cudaFuncSetAttribute(comb_hmma_kernel,
                         cudaFuncAttributeMaxDynamicSharedMemorySize, SMEM_W4);

    // 0) prep
    split_all_kernel<<<dim3(128, 8, 2), dim3(32, 8)>>>(x, xh, xl, xth, xtl);
    split_all_kernel<<<dim3(128, 8, 6), dim3(32, 8)>>>(mem, memh, meml, memth, memtl);
    cvt_split5_kernel<<<dim3(256, 5), 256>>>(
        q_w, qwh, qwl, 65536,
        proj_w, pwh, pwl, 65536,
        fc1_w, f1h, f1l, 262144,
        fc2_w, f2h, f2l, 262144,
        cw, cwh, cwl, 38400);
    tdt_prep_kernel<<<100, 256>>>(tdt1, tdt2, t1h, t1l, t2h, t2l);
    zT_split_kernel<<<dim3(512, 5, 2), dim3(32, 8)>>>(z, zth, ztl);

    // 1) cl (HMMA)
    cl_hmma_kernel<<<dim3(32, 2, 8), 256, SMEM_W8>>>(cwh, cwl, xh, xl, memh, meml, cl);
    // 2) prompt cos -> scale vectors; clT split
    prompt_scale_kernel<<<dim3(TNE / 256, 1, BB), 256>>>(z, cl, p1, p2, cz, cc);
    clT_split_kernel<<<dim3(128, 5, 8), dim3(32, 8)>>>(cl, clth, cltl);
    // 3) combine (HMMA) -> cluster_x_z + center
    comb_hmma_kernel<<<dim3(256, 2, 2), 256, SMEM_W4>>>(
        t1h, t1l, t2h, t2l, zth, ztl, clth, cltl, cz, cc, cxz, ctr);
    // 4) softmax -> bf16 hi/lo
    softmax_kernel<<<BB * TT4 * NC, 256>>>(cxz, softh, softl);
    // 5) cen (HMMA, split-K atomic)
    zero_cen_kernel<<<(307200 + 255) / 256, 256>>>(cen);
    cen_hmma_kernel<<<dim3(2, 2, 64), 256, SMEM_W8>>>(softh, softl, xth, xtl, memth, memtl, cen);
    // 6) gating + LN
    cin_kernel<<<BB * NC, 256>>>(cen, alpha, beta, norm_w, norm_b, cinln);
    // 7) k/v projections (merged)
    gemm_kv_kernel<<<dim3(4, 5, 2), 256>>>(cinln, k_w, k_b, v_w, v_b, kb, vb);
    // 8) q projection
    hmma_gemm_kernel<4><<<dim3(4, 64), 256, SMEM_W4>>>(
        xh, xl, qwh, qwl, q_b, qb, CC, CC, 0.17677669529663687f);
    // 9) attention -> bf16 split
    attn_kernel<<<dim3(N4 / 256, NH, BB), 256>>>(qb, kb, vb, obh, obl);
    // 10) output projection
    hmma_gemm_kernel<4><<<dim3(4, 64), 256, SMEM_W4>>>(
        obh, obl, pwh, pwl, proj_b, oproj, CC, CC, 1.f);
    // 11) out1 = x + LN(oproj), + split
    ln_add_split_kernel<<<BB * N4, 256>>>(x, oproj, norm_w, norm_b, out1, o1h, o1l);
    // 12) fc1
    hmma_gemm_kernel<8><<<dim3(8, 64), 256, SMEM_W8>>>(
        o1h, o1l, f1h, f1l, fc1_b, h1, HID, CC, 1.f);
    // 13) depthwise conv + gelu -> split
    dwconv_gelu_bf16_kernel<<<(BB * N4 * HID + 255) / 256, 256>>>(h1, dw_w, dw_b, gh, gl);
    // 14) fc2
    hmma_gemm_kernel<4><<<dim3(4, 64), 256, SMEM_W4>>>(
        gh, gl, f2h, f2l, fc2_b, h2, CC, HID, 1.f);
    // 15) out = out1 + LN(h2)
    ln_add_kernel<<<BB * N4, 256>>>(out1, h2, norm_w, norm_b, out0);
}